// round 11
// baseline (speedup 1.0000x reference)
#include <cuda_runtime.h>
#include <cuda_bf16.h>
#include <math.h>
#include <stdint.h>

// Problem shape (validated across passing rounds)
#define CB 16
#define CS 1024
#define CH 256
#define CC 2000

__device__ __nv_bfloat16 g_qhi[CB * CC * CH];
__device__ __nv_bfloat16 g_qlo[CB * CC * CH];
__device__ __nv_bfloat16 g_xhi[CB * CS * CH];
__device__ __nv_bfloat16 g_xlo[CB * CS * CH];
__device__ __nv_bfloat16 g_ahi[CB * CC * CS];
__device__ __nv_bfloat16 g_alo[CB * CC * CS];

#define PITCH 72                      // k-major row: 64 bf16 + 8 pad (144 B)
#define TILE_128 (128 * 144)          // 18432 B (128 rows, k-major)
#define PITCHB_BYTES 272              // [k][n] row: 128 bf16 + 8 pad
#define TILEB_LG (64 * PITCHB_BYTES)  // 17408 B

// single-stage smem, 2 CTAs/SM
#define SMEM_SC (1024 + 4 * TILE_128)              // 74752
#define SMEM_LG (2 * TILE_128 + 2 * TILEB_LG)      // 71680

__device__ __forceinline__ uint32_t smem_u32(const void* p) {
    uint32_t a;
    asm("{ .reg .u64 t; cvta.to.shared.u64 t, %1; cvt.u32.u64 %0, t; }" : "=r"(a) : "l"(p));
    return a;
}
__device__ __forceinline__ void cp16(uint32_t dst, const void* src) {
    asm volatile("cp.async.cg.shared.global [%0], [%1], 16;" :: "r"(dst), "l"(src) : "memory");
}
__device__ __forceinline__ void cp_commit() { asm volatile("cp.async.commit_group;" ::: "memory"); }
__device__ __forceinline__ void cp_wait0()  { asm volatile("cp.async.wait_group 0;" ::: "memory"); }

__device__ __forceinline__ void ldsm_x4(uint32_t* r, uint32_t a) {
    asm volatile("ldmatrix.sync.aligned.m8n8.x4.shared.b16 {%0,%1,%2,%3}, [%4];"
                 : "=r"(r[0]), "=r"(r[1]), "=r"(r[2]), "=r"(r[3]) : "r"(a));
}
__device__ __forceinline__ void ldsm_x4_t(uint32_t* r, uint32_t a) {
    asm volatile("ldmatrix.sync.aligned.m8n8.x4.trans.shared.b16 {%0,%1,%2,%3}, [%4];"
                 : "=r"(r[0]), "=r"(r[1]), "=r"(r[2]), "=r"(r[3]) : "r"(a));
}
__device__ __forceinline__ void mma16816(float* d, const uint32_t* a, const uint32_t* b) {
    asm volatile(
        "mma.sync.aligned.m16n8k16.row.col.f32.bf16.bf16.f32 "
        "{%0,%1,%2,%3}, {%4,%5,%6,%7}, {%8,%9}, {%0,%1,%2,%3};"
        : "+f"(d[0]), "+f"(d[1]), "+f"(d[2]), "+f"(d[3])
        : "r"(a[0]), "r"(a[1]), "r"(a[2]), "r"(a[3]), "r"(b[0]), "r"(b[1]));
}
__device__ __forceinline__ void split2u(float a, float b, uint32_t& h, uint32_t& l) {
    __nv_bfloat162 hh, ll;
    hh.x = __float2bfloat16(a); hh.y = __float2bfloat16(b);
    ll.x = __float2bfloat16(a - __bfloat162float(hh.x));
    ll.y = __float2bfloat16(b - __bfloat162float(hh.y));
    h = *(uint32_t*)&hh; l = *(uint32_t*)&ll;
}

// ===========================================================================
// prep: one kernel, fp32 -> bf16 hi/lo for q (gathered) and x
// ===========================================================================
__global__ __launch_bounds__(256) void prep_kernel(
    const int* __restrict__ cand, const float* __restrict__ w,
    const float* __restrict__ x,
    int H, int Lmax, int qtotal4, int xtotal4, int hd4)
{
    int i = blockIdx.x * 256 + threadIdx.x;
    if (i < qtotal4) {
        int row  = i / hd4;
        int col4 = i - row * hd4;
        int lbl = cand[row];
        lbl = lbl < 0 ? 0 : (lbl > Lmax ? Lmax : lbl);
        float4 v = *(const float4*)(w + (size_t)lbl * H + col4 * 4);
        uint32_t h0, l0, h1, l1;
        split2u(v.x, v.y, h0, l0);
        split2u(v.z, v.w, h1, l1);
        *(uint2*)(g_qhi + (size_t)i * 4) = make_uint2(h0, h1);
        *(uint2*)(g_qlo + (size_t)i * 4) = make_uint2(l0, l1);
    } else if (i < qtotal4 + xtotal4) {
        int j = i - qtotal4;
        float4 v = *(const float4*)(x + (size_t)j * 4);
        uint32_t h0, l0, h1, l1;
        split2u(v.x, v.y, h0, l0);
        split2u(v.z, v.w, h1, l1);
        *(uint2*)(g_xhi + (size_t)j * 4) = make_uint2(h0, h1);
        *(uint2*)(g_xlo + (size_t)j * 4) = make_uint2(l0, l1);
    }
}

// ===========================================================================
// Kernel 1: scores = q . x^T (masked -> -inf)
// 256 threads, tile 128c x 128s, single-stage smem, 2 CTAs/SM
// ===========================================================================
__global__ __launch_bounds__(256, 2) void scores_mma_kernel(
    const int* __restrict__ masks, float* __restrict__ attn,
    int B, int S, int H, int C)
{
    extern __shared__ char dsm[];
    const uint32_t sb = smem_u32(dsm);
    int* smask = (int*)dsm;

    const int tid = threadIdx.x;
    const int lane = tid & 31;
    const int wid = tid >> 5;
    const int wm = wid & 3;        // 4 m-groups of 32 c
    const int wn = wid >> 2;       // 2 n-groups of 64 s
    const int b  = blockIdx.z;
    const int c0 = blockIdx.y * 128;
    const int s0 = blockIdx.x * 128;

    if (tid < 128) smask[tid] = masks[(size_t)b * S + s0 + tid];

    const uint32_t uA0 = sb + 1024;
    const uint32_t uA1 = uA0 + TILE_128;
    const uint32_t uB0 = uA1 + TILE_128;
    const uint32_t uB1 = uB0 + TILE_128;

    const int a_r = lane & 15;
    const int a_k = (lane >> 4) * 8;
    const int b_n = (lane & 7) | (((lane >> 4) & 1) << 3);
    const int b_k = ((lane >> 3) & 1) * 8;

    float acc[2][8][4];
    #pragma unroll
    for (int i = 0; i < 2; i++)
        #pragma unroll
        for (int j = 0; j < 8; j++)
            #pragma unroll
            for (int q = 0; q < 4; q++) acc[i][j][q] = 0.f;

    // loader mapping: q=tid*4+j -> row=q>>3 (0..127), c16=q&7
    const int lrow = tid >> 1;
    const int lc16 = (tid & 1) * 4;        // 4 consecutive c16 slots per thread
    int crow = c0 + lrow; if (crow >= C) crow = C - 1;
    const __nv_bfloat16* qh = g_qhi + ((size_t)b * C + crow) * H;
    const __nv_bfloat16* ql = g_qlo + ((size_t)b * C + crow) * H;
    const __nv_bfloat16* xh = g_xhi + ((size_t)b * S + s0 + lrow) * H;
    const __nv_bfloat16* xl = g_xlo + ((size_t)b * S + s0 + lrow) * H;
    const uint32_t lsoff = lrow * 144 + lc16 * 16;

    const int nch = H >> 6;      // 4
    for (int ch = 0; ch < nch; ch++) {
        const int kc = ch << 6;
        #pragma unroll
        for (int j = 0; j < 4; j++) {
            const uint32_t soff = lsoff + j * 16;
            const int go = kc + (lc16 + j) * 8;
            cp16(uA0 + soff, qh + go);
            cp16(uA1 + soff, ql + go);
            cp16(uB0 + soff, xh + go);
            cp16(uB1 + soff, xl + go);
        }
        cp_commit();
        cp_wait0();
        __syncthreads();

        #pragma unroll
        for (int kk = 0; kk < 64; kk += 16) {
            uint32_t aH[2][4], aL[2][4];
            #pragma unroll
            for (int mt = 0; mt < 2; mt++) {
                uint32_t off = (uint32_t)((wm * 32 + mt * 16 + a_r) * PITCH + kk + a_k) * 2;
                ldsm_x4(aH[mt], uA0 + off);
                ldsm_x4(aL[mt], uA1 + off);
            }
            uint32_t bH[4][4], bL[4][4];
            #pragma unroll
            for (int t = 0; t < 4; t++) {
                uint32_t off = (uint32_t)((wn * 64 + t * 16 + b_n) * PITCH + kk + b_k) * 2;
                ldsm_x4(bH[t], uB0 + off);
                ldsm_x4(bL[t], uB1 + off);
            }
            #pragma unroll
            for (int mt = 0; mt < 2; mt++)
                #pragma unroll
                for (int t = 0; t < 4; t++)
                    #pragma unroll
                    for (int hf = 0; hf < 2; hf++) {
                        float* d = acc[mt][2 * t + hf];
                        mma16816(d, aH[mt], &bH[t][hf * 2]);
                        mma16816(d, aH[mt], &bL[t][hf * 2]);
                        mma16816(d, aL[mt], &bH[t][hf * 2]);
                    }
        }
        __syncthreads();
    }

    #pragma unroll
    for (int mt = 0; mt < 2; mt++) {
        const int r0 = wm * 32 + mt * 16 + (lane >> 2);
        #pragma unroll
        for (int nt = 0; nt < 8; nt++) {
            const int sl = wn * 64 + nt * 8 + (lane & 3) * 2;
            const float ninf = -INFINITY;
            float2 o0, o1;
            o0.x = smask[sl]     ? acc[mt][nt][0] : ninf;
            o0.y = smask[sl + 1] ? acc[mt][nt][1] : ninf;
            o1.x = smask[sl]     ? acc[mt][nt][2] : ninf;
            o1.y = smask[sl + 1] ? acc[mt][nt][3] : ninf;
            int c = c0 + r0;
            if (c < C)
                *(float2*)(attn + ((size_t)b * C + c) * S + s0 + sl) = o0;
            if (c + 8 < C)
                *(float2*)(attn + ((size_t)b * C + c + 8) * S + s0 + sl) = o1;
        }
    }
}

// ===========================================================================
// Kernel 2: fused softmax — warp per row, single read, write fp32 + bf16 hi/lo
// ===========================================================================
__global__ __launch_bounds__(256) void softmax_fused_kernel(
    float* __restrict__ attn, int S)
{
    const int lane = threadIdx.x & 31;
    const int wrp  = threadIdx.x >> 5;
    const size_t row = (size_t)blockIdx.x * 8 + wrp;
    float* p = attn + row * (size_t)S;
    const int nf = S >> 7;

    float4 v[8];
    float m = -INFINITY;
    #pragma unroll
    for (int f = 0; f < 8; f++) {
        if (f < nf) {
            v[f] = ((const float4*)p)[lane + (f << 5)];
            m = fmaxf(m, fmaxf(fmaxf(v[f].x, v[f].y), fmaxf(v[f].z, v[f].w)));
        }
    }
    #pragma unroll
    for (int o = 16; o > 0; o >>= 1) m = fmaxf(m, __shfl_xor_sync(0xffffffffu, m, o));

    float s = 0.f;
    #pragma unroll
    for (int f = 0; f < 8; f++) {
        if (f < nf) {
            v[f].x = __expf(v[f].x - m); v[f].y = __expf(v[f].y - m);
            v[f].z = __expf(v[f].z - m); v[f].w = __expf(v[f].w - m);
            s += (v[f].x + v[f].y) + (v[f].z + v[f].w);
        }
    }
    #pragma unroll
    for (int o = 16; o > 0; o >>= 1) s += __shfl_xor_sync(0xffffffffu, s, o);
    const float inv = 1.0f / s;

    __nv_bfloat16* ph = g_ahi + row * (size_t)S;
    __nv_bfloat16* pl = g_alo + row * (size_t)S;
    #pragma unroll
    for (int f = 0; f < 8; f++) {
        if (f < nf) {
            float4 o;
            o.x = v[f].x * inv; o.y = v[f].y * inv;
            o.z = v[f].z * inv; o.w = v[f].w * inv;
            const int idx = lane + (f << 5);
            ((float4*)p)[idx] = o;
            uint32_t h0, l0, h1, l1;
            split2u(o.x, o.y, h0, l0);
            split2u(o.z, o.w, h1, l1);
            ((uint2*)ph)[idx] = make_uint2(h0, h1);
            ((uint2*)pl)[idx] = make_uint2(l0, l1);
        }
    }
}

// ===========================================================================
// Kernel 3: logits = attn . x
// 256 threads, tile 128c x 128h, single-stage smem, 2 CTAs/SM
// ===========================================================================
__global__ __launch_bounds__(256, 2) void logits_mma_kernel(
    float* __restrict__ out, int B, int S, int H, int C)
{
    extern __shared__ char dsm[];
    const uint32_t sb = smem_u32(dsm);

    const int tid = threadIdx.x;
    const int lane = tid & 31;
    const int wid = tid >> 5;
    const int wm = wid & 3;
    const int wn = wid >> 2;
    const int b  = blockIdx.z;
    const int c0 = blockIdx.y * 128;
    const int h0 = blockIdx.x * 128;

    const uint32_t uA0 = sb;
    const uint32_t uA1 = uA0 + TILE_128;
    const uint32_t uB0 = uA1 + TILE_128;
    const uint32_t uB1 = uB0 + TILEB_LG;

    const int a_r = lane & 15;
    const int a_k = (lane >> 4) * 8;

    float acc[2][8][4];
    #pragma unroll
    for (int i = 0; i < 2; i++)
        #pragma unroll
        for (int j = 0; j < 8; j++)
            #pragma unroll
            for (int q = 0; q < 4; q++) acc[i][j][q] = 0.f;

    // A loader: q=tid*4+j -> row=q>>3, c16=q&7  (thread covers 4 consecutive c16)
    const int larow = tid >> 1;
    const int lac16 = (tid & 1) * 4;
    int crow = c0 + larow; if (crow >= C) crow = C - 1;
    const __nv_bfloat16* ah = g_ahi + ((size_t)b * C + crow) * S;
    const __nv_bfloat16* al = g_alo + ((size_t)b * C + crow) * S;
    const uint32_t lasoff = larow * 144 + lac16 * 16;
    // B loader: q=tid*4+j -> row=q>>4 (0..63), c16=q&15; thread covers 4 consecutive c16
    const int lbrow = tid >> 2;
    const int lbc16 = (tid & 3) * 4;
    const uint32_t lbsoff = lbrow * PITCHB_BYTES + lbc16 * 16;

    const int nch = S >> 6;      // 16
    for (int ch = 0; ch < nch; ch++) {
        const int kc = ch << 6;
        #pragma unroll
        for (int j = 0; j < 4; j++) {
            const uint32_t soff = lasoff + j * 16;
            const int go = kc + (lac16 + j) * 8;
            cp16(uA0 + soff, ah + go);
            cp16(uA1 + soff, al + go);
        }
        #pragma unroll
        for (int j = 0; j < 4; j++) {
            const uint32_t soff = lbsoff + j * 16;
            const size_t xo = ((size_t)b * S + kc + lbrow) * H + h0 + (lbc16 + j) * 8;
            cp16(uB0 + soff, g_xhi + xo);
            cp16(uB1 + soff, g_xlo + xo);
        }
        cp_commit();
        cp_wait0();
        __syncthreads();

        #pragma unroll
        for (int kk = 0; kk < 64; kk += 16) {
            uint32_t aH[2][4], aL[2][4];
            #pragma unroll
            for (int mt = 0; mt < 2; mt++) {
                uint32_t off = (uint32_t)((wm * 32 + mt * 16 + a_r) * PITCH + kk + a_k) * 2;
                ldsm_x4(aH[mt], uA0 + off);
                ldsm_x4(aL[mt], uA1 + off);
            }
            uint32_t bH[4][4], bL[4][4];
            #pragma unroll
            for (int t = 0; t < 4; t++) {
                uint32_t off = (uint32_t)(kk + (lane & 15)) * PITCHB_BYTES
                             + (uint32_t)(wn * 64 + t * 16 + ((lane >> 4) << 3)) * 2;
                ldsm_x4_t(bH[t], uB0 + off);
                ldsm_x4_t(bL[t], uB1 + off);
            }
            #pragma unroll
            for (int mt = 0; mt < 2; mt++)
                #pragma unroll
                for (int t = 0; t < 4; t++)
                    #pragma unroll
                    for (int hf = 0; hf < 2; hf++) {
                        float* d = acc[mt][2 * t + hf];
                        mma16816(d, aH[mt], &bH[t][hf * 2]);
                        mma16816(d, aH[mt], &bL[t][hf * 2]);
                        mma16816(d, aL[mt], &bH[t][hf * 2]);
                    }
        }
        __syncthreads();
    }

    #pragma unroll
    for (int mt = 0; mt < 2; mt++) {
        const int r0 = wm * 32 + mt * 16 + (lane >> 2);
        #pragma unroll
        for (int nt = 0; nt < 8; nt++) {
            const int hl = wn * 64 + nt * 8 + (lane & 3) * 2;
            int c = c0 + r0;
            if (c < C)
                *(float2*)(out + ((size_t)b * C + c) * H + h0 + hl) =
                    make_float2(acc[mt][nt][0], acc[mt][nt][1]);
            if (c + 8 < C)
                *(float2*)(out + ((size_t)b * C + c + 8) * H + h0 + hl) =
                    make_float2(acc[mt][nt][2], acc[mt][nt][3]);
        }
    }
}

// ===========================================================================
// Launch
// ===========================================================================
extern "C" void kernel_launch(void* const* d_in, const int* in_sizes, int n_in,
                              void* d_out, int out_size)
{
    const float* x     = (const float*)d_in[0];
    const int*   masks = (const int*)d_in[1];
    const int*   cand  = (const int*)d_in[2];
    const float* w     = (const float*)d_in[3];

    const long long n0 = in_sizes[0];
    const long long n1 = in_sizes[1];
    const long long n2 = in_sizes[2];
    const long long n3 = in_sizes[3];

    const int H  = (int)(n0 / n1);
    const int HS = (int)((long long)out_size / n2);
    const int S  = HS - H;
    const int B  = (int)(n1 / S);
    const int C  = (int)(n2 / B);
    const int Lmax = (int)(n3 / H) - 1;

    float* logits = (float*)d_out;
    float* attn   = logits + (size_t)B * C * H;

    static bool attr_set = false;
    if (!attr_set) {
        cudaFuncSetAttribute(scores_mma_kernel, cudaFuncAttributeMaxDynamicSharedMemorySize, SMEM_SC);
        cudaFuncSetAttribute(logits_mma_kernel, cudaFuncAttributeMaxDynamicSharedMemorySize, SMEM_LG);
        attr_set = true;
    }

    const int qtotal4 = B * C * H / 4;
    const int xtotal4 = B * S * H / 4;
    const int ptotal  = qtotal4 + xtotal4;
    prep_kernel<<<(ptotal + 255) / 256, 256>>>(cand, w, x, H, Lmax, qtotal4, xtotal4, H / 4);

    dim3 g1(S / 128, (C + 127) / 128, B);
    scores_mma_kernel<<<g1, 256, SMEM_SC>>>(masks, attn, B, S, H, C);

    dim3 g2((unsigned)((size_t)B * C / 8));
    softmax_fused_kernel<<<g2, 256>>>(attn, S);

    dim3 g3(H / 128, (C + 127) / 128, B);
    logits_mma_kernel<<<g3, 256, SMEM_LG>>>(logits, B, S, H, C);
}

// round 12
// speedup vs baseline: 1.0502x; 1.0502x over previous
#include <cuda_runtime.h>
#include <cuda_bf16.h>
#include <math.h>
#include <stdint.h>

// Problem shape (validated across passing rounds)
#define CB 16
#define CS 1024
#define CH 256
#define CC 2000

__device__ __nv_bfloat16 g_qhi[CB * CC * CH];
__device__ __nv_bfloat16 g_qlo[CB * CC * CH];
__device__ __nv_bfloat16 g_xhi[CB * CS * CH];
__device__ __nv_bfloat16 g_xlo[CB * CS * CH];
__device__ __nv_bfloat16 g_ahi[CB * CC * CS];
__device__ __nv_bfloat16 g_alo[CB * CC * CS];

#define PITCH 72                 // k-major row: 64 bf16 + 8 pad (144 B)
#define TILE_A (256 * 144)       // 36864 B  (256 rows)
#define TILE_N (128 * 144)       // 18432 B  (128 rows)
#define PITCHB_BYTES 272         // [k][n] row: 128 bf16 + 8 pad
#define TILEB_LG (64 * PITCHB_BYTES)  // 17408 B

#define STAGE_SC (2 * TILE_A + 2 * TILE_N)     // 110592
#define SMEM_SC  (1024 + 2 * STAGE_SC)         // 222208
#define STAGE_LG (2 * TILE_A + 2 * TILEB_LG)   // 108544
#define SMEM_LG  (2 * STAGE_LG)                // 217088

__device__ __forceinline__ uint32_t smem_u32(const void* p) {
    uint32_t a;
    asm("{ .reg .u64 t; cvta.to.shared.u64 t, %1; cvt.u32.u64 %0, t; }" : "=r"(a) : "l"(p));
    return a;
}
__device__ __forceinline__ void cp16(uint32_t dst, const void* src) {
    asm volatile("cp.async.cg.shared.global [%0], [%1], 16;" :: "r"(dst), "l"(src) : "memory");
}
__device__ __forceinline__ void cp_commit() { asm volatile("cp.async.commit_group;" ::: "memory"); }
__device__ __forceinline__ void cp_wait1()  { asm volatile("cp.async.wait_group 1;" ::: "memory"); }
__device__ __forceinline__ void cp_wait0()  { asm volatile("cp.async.wait_group 0;" ::: "memory"); }

__device__ __forceinline__ void ldsm_x4(uint32_t* r, uint32_t a) {
    asm volatile("ldmatrix.sync.aligned.m8n8.x4.shared.b16 {%0,%1,%2,%3}, [%4];"
                 : "=r"(r[0]), "=r"(r[1]), "=r"(r[2]), "=r"(r[3]) : "r"(a));
}
__device__ __forceinline__ void ldsm_x4_t(uint32_t* r, uint32_t a) {
    asm volatile("ldmatrix.sync.aligned.m8n8.x4.trans.shared.b16 {%0,%1,%2,%3}, [%4];"
                 : "=r"(r[0]), "=r"(r[1]), "=r"(r[2]), "=r"(r[3]) : "r"(a));
}
__device__ __forceinline__ void mma16816(float* d, const uint32_t* a, const uint32_t* b) {
    asm volatile(
        "mma.sync.aligned.m16n8k16.row.col.f32.bf16.bf16.f32 "
        "{%0,%1,%2,%3}, {%4,%5,%6,%7}, {%8,%9}, {%0,%1,%2,%3};"
        : "+f"(d[0]), "+f"(d[1]), "+f"(d[2]), "+f"(d[3])
        : "r"(a[0]), "r"(a[1]), "r"(a[2]), "r"(a[3]), "r"(b[0]), "r"(b[1]));
}
__device__ __forceinline__ void split2u(float a, float b, uint32_t& h, uint32_t& l) {
    __nv_bfloat162 hh, ll;
    hh.x = __float2bfloat16(a); hh.y = __float2bfloat16(b);
    ll.x = __float2bfloat16(a - __bfloat162float(hh.x));
    ll.y = __float2bfloat16(b - __bfloat162float(hh.y));
    h = *(uint32_t*)&hh; l = *(uint32_t*)&ll;
}

// ===========================================================================
// prep: one kernel, fp32 -> bf16 hi/lo for q (gathered) and x
// ===========================================================================
__global__ __launch_bounds__(256) void prep_kernel(
    const int* __restrict__ cand, const float* __restrict__ w,
    const float* __restrict__ x,
    int H, int Lmax, int qtotal4, int xtotal4, int hd4)
{
    int i = blockIdx.x * 256 + threadIdx.x;
    if (i < qtotal4) {
        int row  = i / hd4;
        int col4 = i - row * hd4;
        int lbl = cand[row];
        lbl = lbl < 0 ? 0 : (lbl > Lmax ? Lmax : lbl);
        float4 v = *(const float4*)(w + (size_t)lbl * H + col4 * 4);
        uint32_t h0, l0, h1, l1;
        split2u(v.x, v.y, h0, l0);
        split2u(v.z, v.w, h1, l1);
        *(uint2*)(g_qhi + (size_t)i * 4) = make_uint2(h0, h1);
        *(uint2*)(g_qlo + (size_t)i * 4) = make_uint2(l0, l1);
    } else if (i < qtotal4 + xtotal4) {
        int j = i - qtotal4;
        float4 v = *(const float4*)(x + (size_t)j * 4);
        uint32_t h0, l0, h1, l1;
        split2u(v.x, v.y, h0, l0);
        split2u(v.z, v.w, h1, l1);
        *(uint2*)(g_xhi + (size_t)j * 4) = make_uint2(h0, h1);
        *(uint2*)(g_xlo + (size_t)j * 4) = make_uint2(l0, l1);
    }
}

// ===========================================================================
// Kernel 1: scores = q . x^T  (masked -> -inf)
// 512 threads, tile 256c x 128s, K chunk 64, 2-stage cp.async + HMMA
// MMA passes pass-major: 16-deep independent accumulator chains.
// ===========================================================================
__global__ __launch_bounds__(512, 1) void scores_mma_kernel(
    const int* __restrict__ masks, float* __restrict__ attn,
    int B, int S, int H, int C)
{
    extern __shared__ char dsm[];
    const uint32_t sb = smem_u32(dsm);
    int* smask = (int*)dsm;

    const int tid = threadIdx.x;
    const int lane = tid & 31;
    const int wid = tid >> 5;
    const int wm = wid & 7;        // 8 m-groups of 32 c
    const int wn = wid >> 3;       // 2 n-groups of 64 s
    const int b  = blockIdx.z;
    const int c0 = blockIdx.y * 256;
    const int s0 = blockIdx.x * 128;

    if (tid < 128) smask[tid] = masks[(size_t)b * S + s0 + tid];

    const int a_r = lane & 15;
    const int a_k = (lane >> 4) * 8;
    const int b_n = (lane & 7) | (((lane >> 4) & 1) << 3);
    const int b_k = ((lane >> 3) & 1) * 8;

    float acc[2][8][4];
    #pragma unroll
    for (int i = 0; i < 2; i++)
        #pragma unroll
        for (int j = 0; j < 8; j++)
            #pragma unroll
            for (int q = 0; q < 4; q++) acc[i][j][q] = 0.f;

    auto prefetch = [&](int ch, int stg) {
        const int kc = ch << 6;
        const uint32_t A0 = sb + 1024 + stg * STAGE_SC;
        const uint32_t A1 = A0 + TILE_A;
        const uint32_t B0 = A1 + TILE_A;
        const uint32_t B1 = B0 + TILE_N;
        #pragma unroll
        for (int j = 0; j < 4; j++) {          // A: 256 rows x 128B
            const int q = (tid << 2) + j;      // 0..2047
            const int row = q >> 3;
            const int c16 = q & 7;
            const uint32_t soff = row * 144 + c16 * 16;
            int crow = c0 + row; if (crow >= C) crow = C - 1;
            const size_t qo = ((size_t)b * C + crow) * H + kc + c16 * 8;
            cp16(A0 + soff, g_qhi + qo);
            cp16(A1 + soff, g_qlo + qo);
        }
        #pragma unroll
        for (int j = 0; j < 2; j++) {          // B: 128 rows x 128B
            const int q = (tid << 1) + j;      // 0..1023
            const int row = q >> 3;
            const int c16 = q & 7;
            const uint32_t soff = row * 144 + c16 * 16;
            const size_t xo = ((size_t)b * S + s0 + row) * H + kc + c16 * 8;
            cp16(B0 + soff, g_xhi + xo);
            cp16(B1 + soff, g_xlo + xo);
        }
        cp_commit();
    };

    const int nch = H >> 6;      // 4
    prefetch(0, 0);
    for (int ch = 0; ch < nch; ch++) {
        if (ch + 1 < nch) { prefetch(ch + 1, (ch + 1) & 1); cp_wait1(); }
        else cp_wait0();
        __syncthreads();

        const uint32_t uA0 = sb + 1024 + (ch & 1) * STAGE_SC;
        const uint32_t uA1 = uA0 + TILE_A;
        const uint32_t uB0 = uA1 + TILE_A;
        const uint32_t uB1 = uB0 + TILE_N;

        #pragma unroll
        for (int kk = 0; kk < 64; kk += 16) {
            uint32_t aH[2][4], aL[2][4];
            #pragma unroll
            for (int mt = 0; mt < 2; mt++) {
                uint32_t off = (uint32_t)((wm * 32 + mt * 16 + a_r) * PITCH + kk + a_k) * 2;
                ldsm_x4(aH[mt], uA0 + off);
                ldsm_x4(aL[mt], uA1 + off);
            }
            uint32_t bH[4][4], bL[4][4];
            #pragma unroll
            for (int t = 0; t < 4; t++) {
                uint32_t off = (uint32_t)((wn * 64 + t * 16 + b_n) * PITCH + kk + b_k) * 2;
                ldsm_x4(bH[t], uB0 + off);
                ldsm_x4(bL[t], uB1 + off);
            }
            // pass-major: consecutive MMAs hit distinct accumulators
            #pragma unroll
            for (int mt = 0; mt < 2; mt++)
                #pragma unroll
                for (int t = 0; t < 4; t++)
                    #pragma unroll
                    for (int hf = 0; hf < 2; hf++)
                        mma16816(acc[mt][2 * t + hf], aH[mt], &bH[t][hf * 2]);
            #pragma unroll
            for (int mt = 0; mt < 2; mt++)
                #pragma unroll
                for (int t = 0; t < 4; t++)
                    #pragma unroll
                    for (int hf = 0; hf < 2; hf++)
                        mma16816(acc[mt][2 * t + hf], aH[mt], &bL[t][hf * 2]);
            #pragma unroll
            for (int mt = 0; mt < 2; mt++)
                #pragma unroll
                for (int t = 0; t < 4; t++)
                    #pragma unroll
                    for (int hf = 0; hf < 2; hf++)
                        mma16816(acc[mt][2 * t + hf], aL[mt], &bH[t][hf * 2]);
        }
        __syncthreads();
    }

    #pragma unroll
    for (int mt = 0; mt < 2; mt++) {
        const int r0 = wm * 32 + mt * 16 + (lane >> 2);
        #pragma unroll
        for (int nt = 0; nt < 8; nt++) {
            const int sl = wn * 64 + nt * 8 + (lane & 3) * 2;
            const float ninf = -INFINITY;
            float2 o0, o1;
            o0.x = smask[sl]     ? acc[mt][nt][0] : ninf;
            o0.y = smask[sl + 1] ? acc[mt][nt][1] : ninf;
            o1.x = smask[sl]     ? acc[mt][nt][2] : ninf;
            o1.y = smask[sl + 1] ? acc[mt][nt][3] : ninf;
            int c = c0 + r0;
            if (c < C)
                *(float2*)(attn + ((size_t)b * C + c) * S + s0 + sl) = o0;
            if (c + 8 < C)
                *(float2*)(attn + ((size_t)b * C + c + 8) * S + s0 + sl) = o1;
        }
    }
}

// ===========================================================================
// Kernel 2: fused softmax — warp per row, single read, write fp32 + bf16 hi/lo
// ===========================================================================
__global__ __launch_bounds__(256) void softmax_fused_kernel(
    float* __restrict__ attn, int S)
{
    const int lane = threadIdx.x & 31;
    const int wrp  = threadIdx.x >> 5;
    const size_t row = (size_t)blockIdx.x * 8 + wrp;
    float* p = attn + row * (size_t)S;
    const int nf = S >> 7;

    float4 v[8];
    float m = -INFINITY;
    #pragma unroll
    for (int f = 0; f < 8; f++) {
        if (f < nf) {
            v[f] = ((const float4*)p)[lane + (f << 5)];
            m = fmaxf(m, fmaxf(fmaxf(v[f].x, v[f].y), fmaxf(v[f].z, v[f].w)));
        }
    }
    #pragma unroll
    for (int o = 16; o > 0; o >>= 1) m = fmaxf(m, __shfl_xor_sync(0xffffffffu, m, o));

    float s = 0.f;
    #pragma unroll
    for (int f = 0; f < 8; f++) {
        if (f < nf) {
            v[f].x = __expf(v[f].x - m); v[f].y = __expf(v[f].y - m);
            v[f].z = __expf(v[f].z - m); v[f].w = __expf(v[f].w - m);
            s += (v[f].x + v[f].y) + (v[f].z + v[f].w);
        }
    }
    #pragma unroll
    for (int o = 16; o > 0; o >>= 1) s += __shfl_xor_sync(0xffffffffu, s, o);
    const float inv = 1.0f / s;

    __nv_bfloat16* ph = g_ahi + row * (size_t)S;
    __nv_bfloat16* pl = g_alo + row * (size_t)S;
    #pragma unroll
    for (int f = 0; f < 8; f++) {
        if (f < nf) {
            float4 o;
            o.x = v[f].x * inv; o.y = v[f].y * inv;
            o.z = v[f].z * inv; o.w = v[f].w * inv;
            const int idx = lane + (f << 5);
            ((float4*)p)[idx] = o;
            uint32_t h0, l0, h1, l1;
            split2u(o.x, o.y, h0, l0);
            split2u(o.z, o.w, h1, l1);
            ((uint2*)ph)[idx] = make_uint2(h0, h1);
            ((uint2*)pl)[idx] = make_uint2(l0, l1);
        }
    }
}

// ===========================================================================
// Kernel 3: logits = attn . x
// 512 threads, tile 256c x 128h, K chunk 64, 2-stage cp.async + HMMA
// MMA passes pass-major.
// ===========================================================================
__global__ __launch_bounds__(512, 1) void logits_mma_kernel(
    float* __restrict__ out, int B, int S, int H, int C)
{
    extern __shared__ char dsm[];
    const uint32_t sb = smem_u32(dsm);

    const int tid = threadIdx.x;
    const int lane = tid & 31;
    const int wid = tid >> 5;
    const int wm = wid & 7;
    const int wn = wid >> 3;
    const int b  = blockIdx.z;
    const int c0 = blockIdx.y * 256;
    const int h0 = blockIdx.x * 128;

    const int a_r = lane & 15;
    const int a_k = (lane >> 4) * 8;

    float acc[2][8][4];
    #pragma unroll
    for (int i = 0; i < 2; i++)
        #pragma unroll
        for (int j = 0; j < 8; j++)
            #pragma unroll
            for (int q = 0; q < 4; q++) acc[i][j][q] = 0.f;

    auto prefetch = [&](int ch, int stg) {
        const int kc = ch << 6;
        const uint32_t A0 = sb + stg * STAGE_LG;
        const uint32_t A1 = A0 + TILE_A;
        const uint32_t B0 = A1 + TILE_A;
        const uint32_t B1 = B0 + TILEB_LG;
        #pragma unroll
        for (int j = 0; j < 4; j++) {          // A: attention hi/lo [c][s], 256 rows
            const int q = (tid << 2) + j;
            const int row = q >> 3;
            const int c16 = q & 7;
            const uint32_t soff = row * 144 + c16 * 16;
            int crow = c0 + row; if (crow >= C) crow = C - 1;
            const size_t ao = ((size_t)b * C + crow) * S + kc + c16 * 8;
            cp16(A0 + soff, g_ahi + ao);
            cp16(A1 + soff, g_alo + ao);
        }
        #pragma unroll
        for (int j = 0; j < 2; j++) {          // B: x hi/lo [s][h], 64 rows x 256B
            const int q = (tid << 1) + j;      // 0..1023
            const int row = q >> 4;
            const int c16 = q & 15;
            const uint32_t soff = row * PITCHB_BYTES + c16 * 16;
            const size_t xo = ((size_t)b * S + kc + row) * H + h0 + c16 * 8;
            cp16(B0 + soff, g_xhi + xo);
            cp16(B1 + soff, g_xlo + xo);
        }
        cp_commit();
    };

    const int nch = S >> 6;      // 16
    prefetch(0, 0);
    for (int ch = 0; ch < nch; ch++) {
        if (ch + 1 < nch) { prefetch(ch + 1, (ch + 1) & 1); cp_wait1(); }
        else cp_wait0();
        __syncthreads();

        const uint32_t uA0 = sb + (ch & 1) * STAGE_LG;
        const uint32_t uA1 = uA0 + TILE_A;
        const uint32_t uB0 = uA1 + TILE_A;
        const uint32_t uB1 = uB0 + TILEB_LG;

        #pragma unroll
        for (int kk = 0; kk < 64; kk += 16) {
            uint32_t aH[2][4], aL[2][4];
            #pragma unroll
            for (int mt = 0; mt < 2; mt++) {
                uint32_t off = (uint32_t)((wm * 32 + mt * 16 + a_r) * PITCH + kk + a_k) * 2;
                ldsm_x4(aH[mt], uA0 + off);
                ldsm_x4(aL[mt], uA1 + off);
            }
            uint32_t bH[4][4], bL[4][4];
            #pragma unroll
            for (int t = 0; t < 4; t++) {
                uint32_t off = (uint32_t)(kk + (lane & 15)) * PITCHB_BYTES
                             + (uint32_t)(wn * 64 + t * 16 + ((lane >> 4) << 3)) * 2;
                ldsm_x4_t(bH[t], uB0 + off);
                ldsm_x4_t(bL[t], uB1 + off);
            }
            #pragma unroll
            for (int mt = 0; mt < 2; mt++)
                #pragma unroll
                for (int t = 0; t < 4; t++)
                    #pragma unroll
                    for (int hf = 0; hf < 2; hf++)
                        mma16816(acc[mt][2 * t + hf], aH[mt], &bH[t][hf * 2]);
            #pragma unroll
            for (int mt = 0; mt < 2; mt++)
                #pragma unroll
                for (int t = 0; t < 4; t++)
                    #pragma unroll
                    for (int hf = 0; hf < 2; hf++)
                        mma16816(acc[mt][2 * t + hf], aH[mt], &bL[t][hf * 2]);
            #pragma unroll
            for (int mt = 0; mt < 2; mt++)
                #pragma unroll
                for (int t = 0; t < 4; t++)
                    #pragma unroll
                    for (int hf = 0; hf < 2; hf++)
                        mma16816(acc[mt][2 * t + hf], aL[mt], &bH[t][hf * 2]);
        }
        __syncthreads();
    }

    #pragma unroll
    for (int mt = 0; mt < 2; mt++) {
        const int r0 = wm * 32 + mt * 16 + (lane >> 2);
        #pragma unroll
        for (int nt = 0; nt < 8; nt++) {
            const int hl = wn * 64 + nt * 8 + (lane & 3) * 2;
            int c = c0 + r0;
            if (c < C)
                *(float2*)(out + ((size_t)b * C + c) * H + h0 + hl) =
                    make_float2(acc[mt][nt][0], acc[mt][nt][1]);
            if (c + 8 < C)
                *(float2*)(out + ((size_t)b * C + c + 8) * H + h0 + hl) =
                    make_float2(acc[mt][nt][2], acc[mt][nt][3]);
        }
    }
}

// ===========================================================================
// Launch
// ===========================================================================
extern "C" void kernel_launch(void* const* d_in, const int* in_sizes, int n_in,
                              void* d_out, int out_size)
{
    const float* x     = (const float*)d_in[0];
    const int*   masks = (const int*)d_in[1];
    const int*   cand  = (const int*)d_in[2];
    const float* w     = (const float*)d_in[3];

    const long long n0 = in_sizes[0];
    const long long n1 = in_sizes[1];
    const long long n2 = in_sizes[2];
    const long long n3 = in_sizes[3];

    const int H  = (int)(n0 / n1);
    const int HS = (int)((long long)out_size / n2);
    const int S  = HS - H;
    const int B  = (int)(n1 / S);
    const int C  = (int)(n2 / B);
    const int Lmax = (int)(n3 / H) - 1;

    float* logits = (float*)d_out;
    float* attn   = logits + (size_t)B * C * H;

    static bool attr_set = false;
    if (!attr_set) {
        cudaFuncSetAttribute(scores_mma_kernel, cudaFuncAttributeMaxDynamicSharedMemorySize, SMEM_SC);
        cudaFuncSetAttribute(logits_mma_kernel, cudaFuncAttributeMaxDynamicSharedMemorySize, SMEM_LG);
        attr_set = true;
    }

    const int qtotal4 = B * C * H / 4;
    const int xtotal4 = B * S * H / 4;
    const int ptotal  = qtotal4 + xtotal4;
    prep_kernel<<<(ptotal + 255) / 256, 256>>>(cand, w, x, H, Lmax, qtotal4, xtotal4, H / 4);

    dim3 g1(S / 128, (C + 255) / 256, B);
    scores_mma_kernel<<<g1, 512, SMEM_SC>>>(masks, attn, B, S, H, C);

    dim3 g2((unsigned)((size_t)B * C / 8));
    softmax_fused_kernel<<<g2, 256>>>(attn, S);

    dim3 g3(H / 128, (C + 255) / 256, B);
    logits_mma_kernel<<<g3, 512, SMEM_LG>>>(logits, B, S, H, C);
}

// round 13
// speedup vs baseline: 1.3353x; 1.2715x over previous
#include <cuda_runtime.h>
#include <cuda_bf16.h>
#include <math.h>
#include <stdint.h>

// Problem shape (validated across passing rounds)
#define CB 16
#define CS 1024
#define CH 256
#define CC 2000

// ---------------------------------------------------------------------------
// Tiled, SW128-swizzled global scratch. All tiles: rows of 128 bytes (64 bf16,
// one K-chunk), SW128 swizzle baked in so cp.async.bulk lands ldmatrix-ready.
// ---------------------------------------------------------------------------
#define SW128(o) ((o) ^ (((o) >> 3) & 0x70))
#define TILE256B 32768              // 256 rows x 128B
#define TILE128B 16384              // 128 rows x 128B
#define CHUNK_BYTES (2 * TILE256B + 2 * TILE128B)   // 98304

// scores A: q tiles  [b][cblk 8][chunk 4][256x64]
__device__ __nv_bfloat16 g_qt_hi[512 * 16384];
__device__ __nv_bfloat16 g_qt_lo[512 * 16384];
// scores B: x tiles  [b][sblk 8][chunk 4][128x64]
__device__ __nv_bfloat16 g_xs_hi[512 * 8192];
__device__ __nv_bfloat16 g_xs_lo[512 * 8192];
// logits B: x^T tiles [b][hblk 2][chunk 16][128x64]
__device__ __nv_bfloat16 g_xt_hi[512 * 8192];
__device__ __nv_bfloat16 g_xt_lo[512 * 8192];
// logits A: attention tiles [b][cblk 8][chunk 16][256x64]  (written by softmax)
__device__ __nv_bfloat16 g_at_hi[2048 * 16384];
__device__ __nv_bfloat16 g_at_lo[2048 * 16384];

#define SMEM_GEMM (1024 + 2 * CHUNK_BYTES)   // 197632

__device__ __forceinline__ uint32_t smem_u32(const void* p) {
    uint32_t a;
    asm("{ .reg .u64 t; cvta.to.shared.u64 t, %1; cvt.u32.u64 %0, t; }" : "=r"(a) : "l"(p));
    return a;
}
__device__ __forceinline__ void mbar_init(uint32_t a, uint32_t cnt) {
    asm volatile("mbarrier.init.shared.b64 [%0], %1;" :: "r"(a), "r"(cnt) : "memory");
}
__device__ __forceinline__ void mbar_expect_tx(uint32_t a, uint32_t bytes) {
    asm volatile("mbarrier.arrive.expect_tx.shared.b64 _, [%0], %1;"
                 :: "r"(a), "r"(bytes) : "memory");
}
__device__ __forceinline__ void mbar_wait(uint32_t a, uint32_t parity) {
    asm volatile(
        "{\n\t.reg .pred P;\n\t"
        "W_%=:\n\t"
        "mbarrier.try_wait.parity.acquire.cta.shared::cta.b64 P, [%0], %1, 0x989680;\n\t"
        "@P bra.uni D_%=;\n\t"
        "bra.uni W_%=;\n\t"
        "D_%=:\n\t}"
        :: "r"(a), "r"(parity) : "memory");
}
__device__ __forceinline__ void bulk_g2s(uint32_t dst, const void* src, uint32_t bytes, uint32_t mbar) {
    asm volatile(
        "cp.async.bulk.shared::cluster.global.mbarrier::complete_tx::bytes [%0], [%1], %2, [%3];"
        :: "r"(dst), "l"(src), "r"(bytes), "r"(mbar) : "memory");
}
__device__ __forceinline__ void ldsm_x4(uint32_t* r, uint32_t a) {
    asm volatile("ldmatrix.sync.aligned.m8n8.x4.shared.b16 {%0,%1,%2,%3}, [%4];"
                 : "=r"(r[0]), "=r"(r[1]), "=r"(r[2]), "=r"(r[3]) : "r"(a));
}
__device__ __forceinline__ void mma16816(float* d, const uint32_t* a, const uint32_t* b) {
    asm volatile(
        "mma.sync.aligned.m16n8k16.row.col.f32.bf16.bf16.f32 "
        "{%0,%1,%2,%3}, {%4,%5,%6,%7}, {%8,%9}, {%0,%1,%2,%3};"
        : "+f"(d[0]), "+f"(d[1]), "+f"(d[2]), "+f"(d[3])
        : "r"(a[0]), "r"(a[1]), "r"(a[2]), "r"(a[3]), "r"(b[0]), "r"(b[1]));
}
__device__ __forceinline__ void split2u(float a, float b, uint32_t& h, uint32_t& l) {
    __nv_bfloat162 hh, ll;
    hh.x = __float2bfloat16(a); hh.y = __float2bfloat16(b);
    ll.x = __float2bfloat16(a - __bfloat162float(hh.x));
    ll.y = __float2bfloat16(b - __bfloat162float(hh.y));
    h = *(uint32_t*)&hh; l = *(uint32_t*)&ll;
}

// ===========================================================================
// prep: q gather + x (scores-B) -> swizzled tiles
// ===========================================================================
__global__ __launch_bounds__(256) void prep_kernel(
    const int* __restrict__ cand, const float* __restrict__ w,
    const float* __restrict__ x, int Lmax, int qtotal, int xtotal)
{
    int i = blockIdx.x * 256 + threadIdx.x;
    if (i < qtotal) {
        // q: quad = i&63 (k/4), crow = (i>>6)&2047, b = i>>17
        const int quad = i & 63;
        const int crow = (i >> 6) & 2047;
        const int b    = i >> 17;
        const int k = quad * 4, chunk = k >> 6, col = k & 63;
        int c = crow < CC ? crow : CC - 1;
        int lbl = cand[b * CC + c];
        lbl = lbl < 0 ? 0 : (lbl > Lmax ? Lmax : lbl);
        float4 v = *(const float4*)(w + (size_t)lbl * CH + k);
        uint32_t h0, l0, h1, l1;
        split2u(v.x, v.y, h0, l0);
        split2u(v.z, v.w, h1, l1);
        const size_t tb = (size_t)((b * 8 + (crow >> 8)) * 4 + chunk) * TILE256B;
        const uint32_t off = SW128((crow & 255) * 128 + col * 2);
        *(uint2*)((char*)g_qt_hi + tb + off) = make_uint2(h0, h1);
        *(uint2*)((char*)g_qt_lo + tb + off) = make_uint2(l0, l1);
    } else if (i < qtotal + xtotal) {
        const int j = i - qtotal;
        const int quad = j & 63;
        const int s    = (j >> 6) & 1023;
        const int b    = j >> 16;
        const int k = quad * 4, chunk = k >> 6, col = k & 63;
        float4 v = *(const float4*)(x + ((size_t)(b * 1024 + s)) * CH + k);
        uint32_t h0, l0, h1, l1;
        split2u(v.x, v.y, h0, l0);
        split2u(v.z, v.w, h1, l1);
        const size_t tb = (size_t)((b * 8 + (s >> 7)) * 4 + chunk) * TILE128B;
        const uint32_t off = SW128((s & 127) * 128 + col * 2);
        *(uint2*)((char*)g_xs_hi + tb + off) = make_uint2(h0, h1);
        *(uint2*)((char*)g_xs_lo + tb + off) = make_uint2(l0, l1);
    }
}

// ===========================================================================
// transpose: x [s][h] -> x^T tiles [h][s] (logits B), swizzled
// grid = B*2*16, 256 threads. Block = (b, hblk, chunk).
// ===========================================================================
__global__ __launch_bounds__(256) void transpose_kernel(const float* __restrict__ x)
{
    __shared__ float t[64][129];
    const int bid = blockIdx.x;
    const int ch = bid & 15;
    const int hb = (bid >> 4) & 1;
    const int b  = bid >> 5;
    const int s0 = ch * 64;
    const int h0 = hb * 128;
    const int tid = threadIdx.x;

    // load 64 s-rows x 128 h floats
    #pragma unroll
    for (int j = 0; j < 8; j++) {
        const int q = j * 256 + tid;      // 0..2047 float4s
        const int s = q >> 5;             // 32 float4 per s-row
        const int c4 = q & 31;
        float4 v = *(const float4*)(x + ((size_t)(b * 1024 + s0 + s)) * CH + h0 + c4 * 4);
        t[s][c4 * 4 + 0] = v.x; t[s][c4 * 4 + 1] = v.y;
        t[s][c4 * 4 + 2] = v.z; t[s][c4 * 4 + 3] = v.w;
    }
    __syncthreads();

    const int h = tid >> 1;
    const int half = tid & 1;
    const size_t tb = (size_t)((b * 2 + hb) * 16 + ch) * TILE128B;
    #pragma unroll
    for (int g = 0; g < 8; g++) {
        const int scol = half * 32 + g * 4;
        float f0 = t[scol + 0][h], f1 = t[scol + 1][h];
        float f2 = t[scol + 2][h], f3 = t[scol + 3][h];
        uint32_t h01, l01, h23, l23;
        split2u(f0, f1, h01, l01);
        split2u(f2, f3, h23, l23);
        const uint32_t off = SW128(h * 128 + scol * 2);
        *(uint2*)((char*)g_xt_hi + tb + off) = make_uint2(h01, h23);
        *(uint2*)((char*)g_xt_lo + tb + off) = make_uint2(l01, l23);
    }
}

// ===========================================================================
// Kernel 1: scores = q . x^T (masked -> -inf)
// 512 thr, tile 256c x 128s, chunk 64, 2-stage cp.async.bulk + HMMA
// ===========================================================================
__global__ __launch_bounds__(512, 1) void scores_mma_kernel(
    const int* __restrict__ masks, float* __restrict__ attn, int S, int C)
{
    extern __shared__ char dsm[];
    const uint32_t sb = smem_u32(dsm);
    const uint32_t mbar0 = sb;                 // 2 x 8B mbarriers
    int* smask = (int*)(dsm + 16);

    const int tid = threadIdx.x;
    const int lane = tid & 31;
    const int wid = tid >> 5;
    const int wm = wid & 7;
    const int wn = wid >> 3;
    const int b  = blockIdx.z;
    const int cblk = blockIdx.y;
    const int sblk = blockIdx.x;
    const int c0 = cblk * 256;
    const int s0 = sblk * 128;

    if (tid == 0) { mbar_init(mbar0, 1); mbar_init(mbar0 + 8, 1); }
    if (tid < 128) smask[tid] = masks[(size_t)b * S + s0 + tid];
    __syncthreads();

    auto issue = [&](int ch, int stg) {
        const uint32_t base = sb + 1024 + stg * CHUNK_BYTES;
        const uint32_t mb = mbar0 + stg * 8;
        const size_t at = (size_t)((b * 8 + cblk) * 4 + ch) * TILE256B;
        const size_t bt = (size_t)((b * 8 + sblk) * 4 + ch) * TILE128B;
        mbar_expect_tx(mb, CHUNK_BYTES);
        bulk_g2s(base,                        (char*)g_qt_hi + at, TILE256B, mb);
        bulk_g2s(base + TILE256B,             (char*)g_qt_lo + at, TILE256B, mb);
        bulk_g2s(base + 2 * TILE256B,             (char*)g_xs_hi + bt, TILE128B, mb);
        bulk_g2s(base + 2 * TILE256B + TILE128B,  (char*)g_xs_lo + bt, TILE128B, mb);
    };
    if (tid == 0) { issue(0, 0); issue(1, 1); }

    const int a_r = lane & 15;
    const int a_k = (lane >> 4) * 8;
    const int b_n = (lane & 7) | (((lane >> 4) & 1) << 3);
    const int b_k = ((lane >> 3) & 1) * 8;

    float acc[2][8][4];
    #pragma unroll
    for (int i = 0; i < 2; i++)
        #pragma unroll
        for (int j = 0; j < 8; j++)
            #pragma unroll
            for (int q = 0; q < 4; q++) acc[i][j][q] = 0.f;

    int ph[2] = {0, 0};
    const int nch = 4;                        // H/64
    for (int ch = 0; ch < nch; ch++) {
        const int stg = ch & 1;
        mbar_wait(mbar0 + stg * 8, ph[stg]);
        ph[stg] ^= 1;

        const uint32_t uA0 = sb + 1024 + stg * CHUNK_BYTES;
        const uint32_t uA1 = uA0 + TILE256B;
        const uint32_t uB0 = uA1 + TILE256B;
        const uint32_t uB1 = uB0 + TILE128B;

        #pragma unroll
        for (int kk = 0; kk < 64; kk += 16) {
            uint32_t aH[2][4], aL[2][4];
            #pragma unroll
            for (int mt = 0; mt < 2; mt++) {
                uint32_t off = SW128((uint32_t)(wm * 32 + mt * 16 + a_r) * 128 + (kk + a_k) * 2);
                ldsm_x4(aH[mt], uA0 + off);
                ldsm_x4(aL[mt], uA1 + off);
            }
            uint32_t bH[4][4], bL[4][4];
            #pragma unroll
            for (int t = 0; t < 4; t++) {
                uint32_t off = SW128((uint32_t)(wn * 64 + t * 16 + b_n) * 128 + (kk + b_k) * 2);
                ldsm_x4(bH[t], uB0 + off);
                ldsm_x4(bL[t], uB1 + off);
            }
            #pragma unroll
            for (int mt = 0; mt < 2; mt++)
                #pragma unroll
                for (int t = 0; t < 4; t++)
                    #pragma unroll
                    for (int hf = 0; hf < 2; hf++)
                        mma16816(acc[mt][2 * t + hf], aH[mt], &bH[t][hf * 2]);
            #pragma unroll
            for (int mt = 0; mt < 2; mt++)
                #pragma unroll
                for (int t = 0; t < 4; t++)
                    #pragma unroll
                    for (int hf = 0; hf < 2; hf++)
                        mma16816(acc[mt][2 * t + hf], aH[mt], &bL[t][hf * 2]);
            #pragma unroll
            for (int mt = 0; mt < 2; mt++)
                #pragma unroll
                for (int t = 0; t < 4; t++)
                    #pragma unroll
                    for (int hf = 0; hf < 2; hf++)
                        mma16816(acc[mt][2 * t + hf], aL[mt], &bH[t][hf * 2]);
        }
        __syncthreads();
        if (tid == 0 && ch + 2 < nch) issue(ch + 2, stg);
    }

    #pragma unroll
    for (int mt = 0; mt < 2; mt++) {
        const int r0 = wm * 32 + mt * 16 + (lane >> 2);
        #pragma unroll
        for (int nt = 0; nt < 8; nt++) {
            const int sl = wn * 64 + nt * 8 + (lane & 3) * 2;
            const float ninf = -INFINITY;
            float2 o0, o1;
            o0.x = smask[sl]     ? acc[mt][nt][0] : ninf;
            o0.y = smask[sl + 1] ? acc[mt][nt][1] : ninf;
            o1.x = smask[sl]     ? acc[mt][nt][2] : ninf;
            o1.y = smask[sl + 1] ? acc[mt][nt][3] : ninf;
            int c = c0 + r0;
            if (c < C)
                *(float2*)(attn + ((size_t)b * C + c) * S + s0 + sl) = o0;
            if (c + 8 < C)
                *(float2*)(attn + ((size_t)b * C + c + 8) * S + s0 + sl) = o1;
        }
    }
}

// ===========================================================================
// Kernel 2: fused softmax — warp/row; writes fp32 attn + swizzled bf16 tiles
// ===========================================================================
__global__ __launch_bounds__(256) void softmax_fused_kernel(
    float* __restrict__ attn, int S, int C)
{
    const int lane = threadIdx.x & 31;
    const int wrp  = threadIdx.x >> 5;
    const int row = blockIdx.x * 8 + wrp;
    const int b = row / C;
    const int c = row - b * C;
    float* p = attn + (size_t)row * S;

    float4 v[8];
    float m = -INFINITY;
    #pragma unroll
    for (int f = 0; f < 8; f++) {
        v[f] = ((const float4*)p)[lane + (f << 5)];
        m = fmaxf(m, fmaxf(fmaxf(v[f].x, v[f].y), fmaxf(v[f].z, v[f].w)));
    }
    #pragma unroll
    for (int o = 16; o > 0; o >>= 1) m = fmaxf(m, __shfl_xor_sync(0xffffffffu, m, o));

    float s = 0.f;
    #pragma unroll
    for (int f = 0; f < 8; f++) {
        v[f].x = __expf(v[f].x - m); v[f].y = __expf(v[f].y - m);
        v[f].z = __expf(v[f].z - m); v[f].w = __expf(v[f].w - m);
        s += (v[f].x + v[f].y) + (v[f].z + v[f].w);
    }
    #pragma unroll
    for (int o = 16; o > 0; o >>= 1) s += __shfl_xor_sync(0xffffffffu, s, o);
    const float inv = 1.0f / s;

    const size_t tile0 = (size_t)((b * 8 + (c >> 8)) * 16) * TILE256B;
    const uint32_t rowoff = (uint32_t)(c & 255) * 128;
    #pragma unroll
    for (int f = 0; f < 8; f++) {
        float4 o;
        o.x = v[f].x * inv; o.y = v[f].y * inv;
        o.z = v[f].z * inv; o.w = v[f].w * inv;
        const int idx = lane + (f << 5);
        ((float4*)p)[idx] = o;
        uint32_t h0, l0, h1, l1;
        split2u(o.x, o.y, h0, l0);
        split2u(o.z, o.w, h1, l1);
        const int chunk = idx >> 4;                  // s/64
        const uint32_t off = SW128(rowoff + (idx & 15) * 8);
        const size_t byteoff = tile0 + (size_t)chunk * TILE256B + off;
        *(uint2*)((char*)g_at_hi + byteoff) = make_uint2(h0, h1);
        *(uint2*)((char*)g_at_lo + byteoff) = make_uint2(l0, l1);
    }
}

// ===========================================================================
// Kernel 3: logits = attn . x — same structure as scores (B = x^T tiles)
// ===========================================================================
__global__ __launch_bounds__(512, 1) void logits_mma_kernel(
    float* __restrict__ out, int H, int C)
{
    extern __shared__ char dsm[];
    const uint32_t sb = smem_u32(dsm);
    const uint32_t mbar0 = sb;

    const int tid = threadIdx.x;
    const int lane = tid & 31;
    const int wid = tid >> 5;
    const int wm = wid & 7;
    const int wn = wid >> 3;
    const int b  = blockIdx.z;
    const int cblk = blockIdx.y;
    const int hb = blockIdx.x;
    const int c0 = cblk * 256;
    const int h0 = hb * 128;

    if (tid == 0) { mbar_init(mbar0, 1); mbar_init(mbar0 + 8, 1); }
    __syncthreads();

    auto issue = [&](int ch, int stg) {
        const uint32_t base = sb + 1024 + stg * CHUNK_BYTES;
        const uint32_t mb = mbar0 + stg * 8;
        const size_t at = (size_t)((b * 8 + cblk) * 16 + ch) * TILE256B;
        const size_t bt = (size_t)((b * 2 + hb) * 16 + ch) * TILE128B;
        mbar_expect_tx(mb, CHUNK_BYTES);
        bulk_g2s(base,                        (char*)g_at_hi + at, TILE256B, mb);
        bulk_g2s(base + TILE256B,             (char*)g_at_lo + at, TILE256B, mb);
        bulk_g2s(base + 2 * TILE256B,             (char*)g_xt_hi + bt, TILE128B, mb);
        bulk_g2s(base + 2 * TILE256B + TILE128B,  (char*)g_xt_lo + bt, TILE128B, mb);
    };
    if (tid == 0) { issue(0, 0); issue(1, 1); }

    const int a_r = lane & 15;
    const int a_k = (lane >> 4) * 8;
    const int b_n = (lane & 7) | (((lane >> 4) & 1) << 3);
    const int b_k = ((lane >> 3) & 1) * 8;

    float acc[2][8][4];
    #pragma unroll
    for (int i = 0; i < 2; i++)
        #pragma unroll
        for (int j = 0; j < 8; j++)
            #pragma unroll
            for (int q = 0; q < 4; q++) acc[i][j][q] = 0.f;

    int ph[2] = {0, 0};
    const int nch = 16;                      // S/64
    for (int ch = 0; ch < nch; ch++) {
        const int stg = ch & 1;
        mbar_wait(mbar0 + stg * 8, ph[stg]);
        ph[stg] ^= 1;

        const uint32_t uA0 = sb + 1024 + stg * CHUNK_BYTES;
        const uint32_t uA1 = uA0 + TILE256B;
        const uint32_t uB0 = uA1 + TILE256B;
        const uint32_t uB1 = uB0 + TILE128B;

        #pragma unroll
        for (int kk = 0; kk < 64; kk += 16) {
            uint32_t aH[2][4], aL[2][4];
            #pragma unroll
            for (int mt = 0; mt < 2; mt++) {
                uint32_t off = SW128((uint32_t)(wm * 32 + mt * 16 + a_r) * 128 + (kk + a_k) * 2);
                ldsm_x4(aH[mt], uA0 + off);
                ldsm_x4(aL[mt], uA1 + off);
            }
            uint32_t bH[4][4], bL[4][4];
            #pragma unroll
            for (int t = 0; t < 4; t++) {
                uint32_t off = SW128((uint32_t)(wn * 64 + t * 16 + b_n) * 128 + (kk + b_k) * 2);
                ldsm_x4(bH[t], uB0 + off);
                ldsm_x4(bL[t], uB1 + off);
            }
            #pragma unroll
            for (int mt = 0; mt < 2; mt++)
                #pragma unroll
                for (int t = 0; t < 4; t++)
                    #pragma unroll
                    for (int hf = 0; hf < 2; hf++)
                        mma16816(acc[mt][2 * t + hf], aH[mt], &bH[t][hf * 2]);
            #pragma unroll
            for (int mt = 0; mt < 2; mt++)
                #pragma unroll
                for (int t = 0; t < 4; t++)
                    #pragma unroll
                    for (int hf = 0; hf < 2; hf++)
                        mma16816(acc[mt][2 * t + hf], aH[mt], &bL[t][hf * 2]);
            #pragma unroll
            for (int mt = 0; mt < 2; mt++)
                #pragma unroll
                for (int t = 0; t < 4; t++)
                    #pragma unroll
                    for (int hf = 0; hf < 2; hf++)
                        mma16816(acc[mt][2 * t + hf], aL[mt], &bH[t][hf * 2]);
        }
        __syncthreads();
        if (tid == 0 && ch + 2 < nch) issue(ch + 2, stg);
    }

    #pragma unroll
    for (int mt = 0; mt < 2; mt++) {
        const int r0 = wm * 32 + mt * 16 + (lane >> 2);
        #pragma unroll
        for (int nt = 0; nt < 8; nt++) {
            const int hl = wn * 64 + nt * 8 + (lane & 3) * 2;
            int c = c0 + r0;
            if (c < C)
                *(float2*)(out + ((size_t)b * C + c) * H + h0 + hl) =
                    make_float2(acc[mt][nt][0], acc[mt][nt][1]);
            if (c + 8 < C)
                *(float2*)(out + ((size_t)b * C + c + 8) * H + h0 + hl) =
                    make_float2(acc[mt][nt][2], acc[mt][nt][3]);
        }
    }
}

// ===========================================================================
// Launch
// ===========================================================================
extern "C" void kernel_launch(void* const* d_in, const int* in_sizes, int n_in,
                              void* d_out, int out_size)
{
    const float* x     = (const float*)d_in[0];
    const int*   masks = (const int*)d_in[1];
    const int*   cand  = (const int*)d_in[2];
    const float* w     = (const float*)d_in[3];

    const long long n0 = in_sizes[0];
    const long long n1 = in_sizes[1];
    const long long n2 = in_sizes[2];
    const long long n3 = in_sizes[3];

    const int H  = (int)(n0 / n1);
    const int HS = (int)((long long)out_size / n2);
    const int S  = HS - H;
    const int B  = (int)(n1 / S);
    const int C  = (int)(n2 / B);
    const int Lmax = (int)(n3 / H) - 1;

    float* logits = (float*)d_out;
    float* attn   = logits + (size_t)B * C * H;

    static bool attr_set = false;
    if (!attr_set) {
        cudaFuncSetAttribute(scores_mma_kernel, cudaFuncAttributeMaxDynamicSharedMemorySize, SMEM_GEMM);
        cudaFuncSetAttribute(logits_mma_kernel, cudaFuncAttributeMaxDynamicSharedMemorySize, SMEM_GEMM);
        attr_set = true;
    }

    const int qtotal = B * 2048 * 64;    // quads
    const int xtotal = B * 1024 * 64;
    prep_kernel<<<(qtotal + xtotal + 255) / 256, 256>>>(cand, w, x, Lmax, qtotal, xtotal);

    transpose_kernel<<<B * 2 * 16, 256>>>(x);

    dim3 g1(S / 128, 8, B);
    scores_mma_kernel<<<g1, 512, SMEM_GEMM>>>(masks, attn, S, C);

    dim3 g2((unsigned)((size_t)B * C / 8));
    softmax_fused_kernel<<<g2, 256>>>(attn, S, C);

    dim3 g3(H / 128, 8, B);
    logits_mma_kernel<<<g3, 512, SMEM_GEMM>>>(logits, H, C);
}

// round 14
// speedup vs baseline: 1.7783x; 1.3317x over previous
#include <cuda_runtime.h>
#include <cuda_bf16.h>
#include <cuda_fp16.h>
#include <math.h>
#include <stdint.h>

// Problem shape (validated across passing rounds)
#define CB 16
#define CS 1024
#define CH 256
#define CC 2000

// ---------------------------------------------------------------------------
// Tiled, SW128-swizzled global scratch. Rows of 128 bytes (one 64-elem K-chunk),
// SW128 baked in so cp.async.bulk lands ldmatrix-ready.
// ---------------------------------------------------------------------------
#define SW128(o) ((o) ^ (((o) >> 3) & 0x70))
#define TILE256B 32768              // 256 rows x 128B
#define TILE128B 16384              // 128 rows x 128B
#define CHUNK_SC (2 * TILE256B + 2 * TILE128B)   // 98304 (scores: bf16 hi/lo)
#define CHUNK_LG (TILE256B + TILE128B)           // 49152 (logits: fp16 single)

// scores A: q tiles  [b][cblk 8][chunk 4][256x64] bf16 hi/lo
__device__ __nv_bfloat16 g_qt_hi[512 * 16384];
__device__ __nv_bfloat16 g_qt_lo[512 * 16384];
// scores B: x tiles  [b][sblk 8][chunk 4][128x64] bf16 hi/lo
__device__ __nv_bfloat16 g_xs_hi[512 * 8192];
__device__ __nv_bfloat16 g_xs_lo[512 * 8192];
// logits B: x^T tiles [b][hblk 2][chunk 16][128x64] fp16
__device__ __half g_xt_f16[512 * 8192];
// logits A: attention tiles [b][cblk 8][chunk 16][256x64] fp16 (from softmax)
__device__ __half g_at_f16[2048 * 16384];

#define SMEM_SC (1024 + 2 * CHUNK_SC)   // 197632
#define SMEM_LG (1024 + 2 * CHUNK_LG)   // 99328

__device__ __forceinline__ uint32_t smem_u32(const void* p) {
    uint32_t a;
    asm("{ .reg .u64 t; cvta.to.shared.u64 t, %1; cvt.u32.u64 %0, t; }" : "=r"(a) : "l"(p));
    return a;
}
__device__ __forceinline__ void mbar_init(uint32_t a, uint32_t cnt) {
    asm volatile("mbarrier.init.shared.b64 [%0], %1;" :: "r"(a), "r"(cnt) : "memory");
}
__device__ __forceinline__ void mbar_expect_tx(uint32_t a, uint32_t bytes) {
    asm volatile("mbarrier.arrive.expect_tx.shared.b64 _, [%0], %1;"
                 :: "r"(a), "r"(bytes) : "memory");
}
__device__ __forceinline__ void mbar_wait(uint32_t a, uint32_t parity) {
    asm volatile(
        "{\n\t.reg .pred P;\n\t"
        "W_%=:\n\t"
        "mbarrier.try_wait.parity.acquire.cta.shared::cta.b64 P, [%0], %1, 0x989680;\n\t"
        "@P bra.uni D_%=;\n\t"
        "bra.uni W_%=;\n\t"
        "D_%=:\n\t}"
        :: "r"(a), "r"(parity) : "memory");
}
__device__ __forceinline__ void bulk_g2s(uint32_t dst, const void* src, uint32_t bytes, uint32_t mbar) {
    asm volatile(
        "cp.async.bulk.shared::cluster.global.mbarrier::complete_tx::bytes [%0], [%1], %2, [%3];"
        :: "r"(dst), "l"(src), "r"(bytes), "r"(mbar) : "memory");
}
__device__ __forceinline__ void ldsm_x4(uint32_t* r, uint32_t a) {
    asm volatile("ldmatrix.sync.aligned.m8n8.x4.shared.b16 {%0,%1,%2,%3}, [%4];"
                 : "=r"(r[0]), "=r"(r[1]), "=r"(r[2]), "=r"(r[3]) : "r"(a));
}
__device__ __forceinline__ void mma16816(float* d, const uint32_t* a, const uint32_t* b) {
    asm volatile(
        "mma.sync.aligned.m16n8k16.row.col.f32.bf16.bf16.f32 "
        "{%0,%1,%2,%3}, {%4,%5,%6,%7}, {%8,%9}, {%0,%1,%2,%3};"
        : "+f"(d[0]), "+f"(d[1]), "+f"(d[2]), "+f"(d[3])
        : "r"(a[0]), "r"(a[1]), "r"(a[2]), "r"(a[3]), "r"(b[0]), "r"(b[1]));
}
__device__ __forceinline__ void mma16816_f16(float* d, const uint32_t* a, const uint32_t* b) {
    asm volatile(
        "mma.sync.aligned.m16n8k16.row.col.f32.f16.f16.f32 "
        "{%0,%1,%2,%3}, {%4,%5,%6,%7}, {%8,%9}, {%0,%1,%2,%3};"
        : "+f"(d[0]), "+f"(d[1]), "+f"(d[2]), "+f"(d[3])
        : "r"(a[0]), "r"(a[1]), "r"(a[2]), "r"(a[3]), "r"(b[0]), "r"(b[1]));
}
__device__ __forceinline__ void split2u(float a, float b, uint32_t& h, uint32_t& l) {
    __nv_bfloat162 hh, ll;
    hh.x = __float2bfloat16(a); hh.y = __float2bfloat16(b);
    ll.x = __float2bfloat16(a - __bfloat162float(hh.x));
    ll.y = __float2bfloat16(b - __bfloat162float(hh.y));
    h = *(uint32_t*)&hh; l = *(uint32_t*)&ll;
}
__device__ __forceinline__ uint32_t pack_h2(float a, float b) {
    __half2 p = __floats2half2_rn(a, b);
    return *(uint32_t*)&p;
}

// ===========================================================================
// prep: q gather + x (scores-B) -> swizzled bf16 hi/lo tiles
// ===========================================================================
__global__ __launch_bounds__(256) void prep_kernel(
    const int* __restrict__ cand, const float* __restrict__ w,
    const float* __restrict__ x, int Lmax, int qtotal, int xtotal)
{
    int i = blockIdx.x * 256 + threadIdx.x;
    if (i < qtotal) {
        const int quad = i & 63;
        const int crow = (i >> 6) & 2047;
        const int b    = i >> 17;
        const int k = quad * 4, chunk = k >> 6, col = k & 63;
        int c = crow < CC ? crow : CC - 1;
        int lbl = cand[b * CC + c];
        lbl = lbl < 0 ? 0 : (lbl > Lmax ? Lmax : lbl);
        float4 v = *(const float4*)(w + (size_t)lbl * CH + k);
        uint32_t h0, l0, h1, l1;
        split2u(v.x, v.y, h0, l0);
        split2u(v.z, v.w, h1, l1);
        const size_t tb = (size_t)((b * 8 + (crow >> 8)) * 4 + chunk) * TILE256B;
        const uint32_t off = SW128((crow & 255) * 128 + col * 2);
        *(uint2*)((char*)g_qt_hi + tb + off) = make_uint2(h0, h1);
        *(uint2*)((char*)g_qt_lo + tb + off) = make_uint2(l0, l1);
    } else if (i < qtotal + xtotal) {
        const int j = i - qtotal;
        const int quad = j & 63;
        const int s    = (j >> 6) & 1023;
        const int b    = j >> 16;
        const int k = quad * 4, chunk = k >> 6, col = k & 63;
        float4 v = *(const float4*)(x + ((size_t)(b * 1024 + s)) * CH + k);
        uint32_t h0, l0, h1, l1;
        split2u(v.x, v.y, h0, l0);
        split2u(v.z, v.w, h1, l1);
        const size_t tb = (size_t)((b * 8 + (s >> 7)) * 4 + chunk) * TILE128B;
        const uint32_t off = SW128((s & 127) * 128 + col * 2);
        *(uint2*)((char*)g_xs_hi + tb + off) = make_uint2(h0, h1);
        *(uint2*)((char*)g_xs_lo + tb + off) = make_uint2(l0, l1);
    }
}

// ===========================================================================
// transpose: x [s][h] -> x^T fp16 tiles [h][s] (logits B), swizzled
// ===========================================================================
__global__ __launch_bounds__(256) void transpose_kernel(const float* __restrict__ x)
{
    __shared__ float t[64][129];
    const int bid = blockIdx.x;
    const int ch = bid & 15;
    const int hb = (bid >> 4) & 1;
    const int b  = bid >> 5;
    const int s0 = ch * 64;
    const int h0 = hb * 128;
    const int tid = threadIdx.x;

    #pragma unroll
    for (int j = 0; j < 8; j++) {
        const int q = j * 256 + tid;
        const int s = q >> 5;
        const int c4 = q & 31;
        float4 v = *(const float4*)(x + ((size_t)(b * 1024 + s0 + s)) * CH + h0 + c4 * 4);
        t[s][c4 * 4 + 0] = v.x; t[s][c4 * 4 + 1] = v.y;
        t[s][c4 * 4 + 2] = v.z; t[s][c4 * 4 + 3] = v.w;
    }
    __syncthreads();

    const int h = tid >> 1;
    const int half = tid & 1;
    const size_t tb = (size_t)((b * 2 + hb) * 16 + ch) * TILE128B;
    #pragma unroll
    for (int g = 0; g < 8; g++) {
        const int scol = half * 32 + g * 4;
        uint32_t p01 = pack_h2(t[scol + 0][h], t[scol + 1][h]);
        uint32_t p23 = pack_h2(t[scol + 2][h], t[scol + 3][h]);
        const uint32_t off = SW128(h * 128 + scol * 2);
        *(uint2*)((char*)g_xt_f16 + tb + off) = make_uint2(p01, p23);
    }
}

// ===========================================================================
// Kernel 1: scores = q . x^T (masked -> -inf), bf16 3-pass (unchanged)
// ===========================================================================
__global__ __launch_bounds__(512, 1) void scores_mma_kernel(
    const int* __restrict__ masks, float* __restrict__ attn, int S, int C)
{
    extern __shared__ char dsm[];
    const uint32_t sb = smem_u32(dsm);
    const uint32_t mbar0 = sb;
    int* smask = (int*)(dsm + 16);

    const int tid = threadIdx.x;
    const int lane = tid & 31;
    const int wid = tid >> 5;
    const int wm = wid & 7;
    const int wn = wid >> 3;
    const int b  = blockIdx.z;
    const int cblk = blockIdx.y;
    const int sblk = blockIdx.x;
    const int c0 = cblk * 256;
    const int s0 = sblk * 128;

    if (tid == 0) { mbar_init(mbar0, 1); mbar_init(mbar0 + 8, 1); }
    if (tid < 128) smask[tid] = masks[(size_t)b * S + s0 + tid];
    __syncthreads();

    auto issue = [&](int ch, int stg) {
        const uint32_t base = sb + 1024 + stg * CHUNK_SC;
        const uint32_t mb = mbar0 + stg * 8;
        const size_t at = (size_t)((b * 8 + cblk) * 4 + ch) * TILE256B;
        const size_t bt = (size_t)((b * 8 + sblk) * 4 + ch) * TILE128B;
        mbar_expect_tx(mb, CHUNK_SC);
        bulk_g2s(base,                        (char*)g_qt_hi + at, TILE256B, mb);
        bulk_g2s(base + TILE256B,             (char*)g_qt_lo + at, TILE256B, mb);
        bulk_g2s(base + 2 * TILE256B,             (char*)g_xs_hi + bt, TILE128B, mb);
        bulk_g2s(base + 2 * TILE256B + TILE128B,  (char*)g_xs_lo + bt, TILE128B, mb);
    };
    if (tid == 0) { issue(0, 0); issue(1, 1); }

    const int a_r = lane & 15;
    const int a_k = (lane >> 4) * 8;
    const int b_n = (lane & 7) | (((lane >> 4) & 1) << 3);
    const int b_k = ((lane >> 3) & 1) * 8;

    float acc[2][8][4];
    #pragma unroll
    for (int i = 0; i < 2; i++)
        #pragma unroll
        for (int j = 0; j < 8; j++)
            #pragma unroll
            for (int q = 0; q < 4; q++) acc[i][j][q] = 0.f;

    int ph[2] = {0, 0};
    const int nch = 4;
    for (int ch = 0; ch < nch; ch++) {
        const int stg = ch & 1;
        mbar_wait(mbar0 + stg * 8, ph[stg]);
        ph[stg] ^= 1;

        const uint32_t uA0 = sb + 1024 + stg * CHUNK_SC;
        const uint32_t uA1 = uA0 + TILE256B;
        const uint32_t uB0 = uA1 + TILE256B;
        const uint32_t uB1 = uB0 + TILE128B;

        #pragma unroll
        for (int kk = 0; kk < 64; kk += 16) {
            uint32_t aH[2][4], aL[2][4];
            #pragma unroll
            for (int mt = 0; mt < 2; mt++) {
                uint32_t off = SW128((uint32_t)(wm * 32 + mt * 16 + a_r) * 128 + (kk + a_k) * 2);
                ldsm_x4(aH[mt], uA0 + off);
                ldsm_x4(aL[mt], uA1 + off);
            }
            uint32_t bH[4][4], bL[4][4];
            #pragma unroll
            for (int t = 0; t < 4; t++) {
                uint32_t off = SW128((uint32_t)(wn * 64 + t * 16 + b_n) * 128 + (kk + b_k) * 2);
                ldsm_x4(bH[t], uB0 + off);
                ldsm_x4(bL[t], uB1 + off);
            }
            #pragma unroll
            for (int mt = 0; mt < 2; mt++)
                #pragma unroll
                for (int t = 0; t < 4; t++)
                    #pragma unroll
                    for (int hf = 0; hf < 2; hf++)
                        mma16816(acc[mt][2 * t + hf], aH[mt], &bH[t][hf * 2]);
            #pragma unroll
            for (int mt = 0; mt < 2; mt++)
                #pragma unroll
                for (int t = 0; t < 4; t++)
                    #pragma unroll
                    for (int hf = 0; hf < 2; hf++)
                        mma16816(acc[mt][2 * t + hf], aH[mt], &bL[t][hf * 2]);
            #pragma unroll
            for (int mt = 0; mt < 2; mt++)
                #pragma unroll
                for (int t = 0; t < 4; t++)
                    #pragma unroll
                    for (int hf = 0; hf < 2; hf++)
                        mma16816(acc[mt][2 * t + hf], aL[mt], &bH[t][hf * 2]);
        }
        __syncthreads();
        if (tid == 0 && ch + 2 < nch) issue(ch + 2, stg);
    }

    #pragma unroll
    for (int mt = 0; mt < 2; mt++) {
        const int r0 = wm * 32 + mt * 16 + (lane >> 2);
        #pragma unroll
        for (int nt = 0; nt < 8; nt++) {
            const int sl = wn * 64 + nt * 8 + (lane & 3) * 2;
            const float ninf = -INFINITY;
            float2 o0, o1;
            o0.x = smask[sl]     ? acc[mt][nt][0] : ninf;
            o0.y = smask[sl + 1] ? acc[mt][nt][1] : ninf;
            o1.x = smask[sl]     ? acc[mt][nt][2] : ninf;
            o1.y = smask[sl + 1] ? acc[mt][nt][3] : ninf;
            int c = c0 + r0;
            if (c < C)
                *(float2*)(attn + ((size_t)b * C + c) * S + s0 + sl) = o0;
            if (c + 8 < C)
                *(float2*)(attn + ((size_t)b * C + c + 8) * S + s0 + sl) = o1;
        }
    }
}

// ===========================================================================
// Kernel 2: fused softmax — warp/row; writes fp32 attn + swizzled fp16 tiles
// ===========================================================================
__global__ __launch_bounds__(256) void softmax_fused_kernel(
    float* __restrict__ attn, int S, int C)
{
    const int lane = threadIdx.x & 31;
    const int wrp  = threadIdx.x >> 5;
    const int row = blockIdx.x * 8 + wrp;
    const int b = row / C;
    const int c = row - b * C;
    float* p = attn + (size_t)row * S;

    float4 v[8];
    float m = -INFINITY;
    #pragma unroll
    for (int f = 0; f < 8; f++) {
        v[f] = ((const float4*)p)[lane + (f << 5)];
        m = fmaxf(m, fmaxf(fmaxf(v[f].x, v[f].y), fmaxf(v[f].z, v[f].w)));
    }
    #pragma unroll
    for (int o = 16; o > 0; o >>= 1) m = fmaxf(m, __shfl_xor_sync(0xffffffffu, m, o));

    float s = 0.f;
    #pragma unroll
    for (int f = 0; f < 8; f++) {
        v[f].x = __expf(v[f].x - m); v[f].y = __expf(v[f].y - m);
        v[f].z = __expf(v[f].z - m); v[f].w = __expf(v[f].w - m);
        s += (v[f].x + v[f].y) + (v[f].z + v[f].w);
    }
    #pragma unroll
    for (int o = 16; o > 0; o >>= 1) s += __shfl_xor_sync(0xffffffffu, s, o);
    const float inv = 1.0f / s;

    const size_t tile0 = (size_t)((b * 8 + (c >> 8)) * 16) * TILE256B;
    const uint32_t rowoff = (uint32_t)(c & 255) * 128;
    #pragma unroll
    for (int f = 0; f < 8; f++) {
        float4 o;
        o.x = v[f].x * inv; o.y = v[f].y * inv;
        o.z = v[f].z * inv; o.w = v[f].w * inv;
        const int idx = lane + (f << 5);
        ((float4*)p)[idx] = o;
        const int chunk = idx >> 4;
        const uint32_t off = SW128(rowoff + (idx & 15) * 8);
        const size_t byteoff = tile0 + (size_t)chunk * TILE256B + off;
        *(uint2*)((char*)g_at_f16 + byteoff) =
            make_uint2(pack_h2(o.x, o.y), pack_h2(o.z, o.w));
    }
}

// ===========================================================================
// Kernel 3: logits = attn . x — single-pass fp16 HMMA, bulk-copy pipeline
// ===========================================================================
__global__ __launch_bounds__(512, 1) void logits_mma_kernel(
    float* __restrict__ out, int H, int C)
{
    extern __shared__ char dsm[];
    const uint32_t sb = smem_u32(dsm);
    const uint32_t mbar0 = sb;

    const int tid = threadIdx.x;
    const int lane = tid & 31;
    const int wid = tid >> 5;
    const int wm = wid & 7;
    const int wn = wid >> 3;
    const int b  = blockIdx.z;
    const int cblk = blockIdx.y;
    const int hb = blockIdx.x;
    const int c0 = cblk * 256;
    const int h0 = hb * 128;

    if (tid == 0) { mbar_init(mbar0, 1); mbar_init(mbar0 + 8, 1); }
    __syncthreads();

    auto issue = [&](int ch, int stg) {
        const uint32_t base = sb + 1024 + stg * CHUNK_LG;
        const uint32_t mb = mbar0 + stg * 8;
        const size_t at = (size_t)((b * 8 + cblk) * 16 + ch) * TILE256B;
        const size_t bt = (size_t)((b * 2 + hb) * 16 + ch) * TILE128B;
        mbar_expect_tx(mb, CHUNK_LG);
        bulk_g2s(base,            (char*)g_at_f16 + at, TILE256B, mb);
        bulk_g2s(base + TILE256B, (char*)g_xt_f16 + bt, TILE128B, mb);
    };
    if (tid == 0) { issue(0, 0); issue(1, 1); }

    const int a_r = lane & 15;
    const int a_k = (lane >> 4) * 8;
    const int b_n = (lane & 7) | (((lane >> 4) & 1) << 3);
    const int b_k = ((lane >> 3) & 1) * 8;

    float acc[2][8][4];
    #pragma unroll
    for (int i = 0; i < 2; i++)
        #pragma unroll
        for (int j = 0; j < 8; j++)
            #pragma unroll
            for (int q = 0; q < 4; q++) acc[i][j][q] = 0.f;

    int ph[2] = {0, 0};
    const int nch = 16;
    for (int ch = 0; ch < nch; ch++) {
        const int stg = ch & 1;
        mbar_wait(mbar0 + stg * 8, ph[stg]);
        ph[stg] ^= 1;

        const uint32_t uA = sb + 1024 + stg * CHUNK_LG;
        const uint32_t uB = uA + TILE256B;

        #pragma unroll
        for (int kk = 0; kk < 64; kk += 16) {
            uint32_t aF[2][4];
            #pragma unroll
            for (int mt = 0; mt < 2; mt++) {
                uint32_t off = SW128((uint32_t)(wm * 32 + mt * 16 + a_r) * 128 + (kk + a_k) * 2);
                ldsm_x4(aF[mt], uA + off);
            }
            uint32_t bF[4][4];
            #pragma unroll
            for (int t = 0; t < 4; t++) {
                uint32_t off = SW128((uint32_t)(wn * 64 + t * 16 + b_n) * 128 + (kk + b_k) * 2);
                ldsm_x4(bF[t], uB + off);
            }
            #pragma unroll
            for (int mt = 0; mt < 2; mt++)
                #pragma unroll
                for (int t = 0; t < 4; t++)
                    #pragma unroll
                    for (int hf = 0; hf < 2; hf++)
                        mma16816_f16(acc[mt][2 * t + hf], aF[mt], &bF[t][hf * 2]);
        }
        __syncthreads();
        if (tid == 0 && ch + 2 < nch) issue(ch + 2, stg);
    }

    #pragma unroll
    for (int mt = 0; mt < 2; mt++) {
        const int r0 = wm * 32 + mt * 16 + (lane >> 2);
        #pragma unroll
        for (int nt = 0; nt < 8; nt++) {
            const int hl = wn * 64 + nt * 8 + (lane & 3) * 2;
            int c = c0 + r0;
            if (c < C)
                *(float2*)(out + ((size_t)b * C + c) * H + h0 + hl) =
                    make_float2(acc[mt][nt][0], acc[mt][nt][1]);
            if (c + 8 < C)
                *(float2*)(out + ((size_t)b * C + c + 8) * H + h0 + hl) =
                    make_float2(acc[mt][nt][2], acc[mt][nt][3]);
        }
    }
}

// ===========================================================================
// Launch
// ===========================================================================
extern "C" void kernel_launch(void* const* d_in, const int* in_sizes, int n_in,
                              void* d_out, int out_size)
{
    const float* x     = (const float*)d_in[0];
    const int*   masks = (const int*)d_in[1];
    const int*   cand  = (const int*)d_in[2];
    const float* w     = (const float*)d_in[3];

    const long long n0 = in_sizes[0];
    const long long n1 = in_sizes[1];
    const long long n2 = in_sizes[2];
    const long long n3 = in_sizes[3];

    const int H  = (int)(n0 / n1);
    const int HS = (int)((long long)out_size / n2);
    const int S  = HS - H;
    const int B  = (int)(n1 / S);
    const int C  = (int)(n2 / B);
    const int Lmax = (int)(n3 / H) - 1;

    float* logits = (float*)d_out;
    float* attn   = logits + (size_t)B * C * H;

    static bool attr_set = false;
    if (!attr_set) {
        cudaFuncSetAttribute(scores_mma_kernel, cudaFuncAttributeMaxDynamicSharedMemorySize, SMEM_SC);
        cudaFuncSetAttribute(logits_mma_kernel, cudaFuncAttributeMaxDynamicSharedMemorySize, SMEM_LG);
        attr_set = true;
    }

    const int qtotal = B * 2048 * 64;
    const int xtotal = B * 1024 * 64;
    prep_kernel<<<(qtotal + xtotal + 255) / 256, 256>>>(cand, w, x, Lmax, qtotal, xtotal);

    transpose_kernel<<<B * 2 * 16, 256>>>(x);

    dim3 g1(S / 128, 8, B);
    scores_mma_kernel<<<g1, 512, SMEM_SC>>>(masks, attn, S, C);

    dim3 g2((unsigned)((size_t)B * C / 8));
    softmax_fused_kernel<<<g2, 256>>>(attn, S, C);

    dim3 g3(H / 128, 8, B);
    logits_mma_kernel<<<g3, 512, SMEM_LG>>>(logits, H, C);
}

// round 15
// speedup vs baseline: 1.7809x; 1.0015x over previous
#include <cuda_runtime.h>
#include <cuda_bf16.h>
#include <cuda_fp16.h>
#include <math.h>
#include <stdint.h>

// Problem shape (validated across passing rounds)
#define CB 16
#define CS 1024
#define CH 256
#define CC 2000

#define SW128(o) ((o) ^ (((o) >> 3) & 0x70))
#define TILE256B 32768              // 256 rows x 128B
#define TILE128B 16384              // 128 rows x 128B
#define CHUNK_SC (2 * TILE256B + 2 * TILE128B)   // 98304 (scores: bf16 hi/lo)
#define CHUNK_LG (TILE256B + TILE128B)           // 49152 (logits: fp16 single)

// scores A: q tiles  [b][cblk 8][chunk 4][256x64] bf16 hi/lo
__device__ __nv_bfloat16 g_qt_hi[512 * 16384];
__device__ __nv_bfloat16 g_qt_lo[512 * 16384];
// scores B: x tiles  [b][sblk 8][chunk 4][128x64] bf16 hi/lo
__device__ __nv_bfloat16 g_xs_hi[512 * 8192];
__device__ __nv_bfloat16 g_xs_lo[512 * 8192];
// logits B: x^T tiles [b][hblk 2][chunk 16][128x64] fp16
__device__ __half g_xt_f16[512 * 8192];
// logits A: attention tiles [b][cblk 8][chunk 16][256x64] fp16 (from softmax)
__device__ __half g_at_f16[2048 * 16384];

#define SMEM_SC (1024 + 2 * CHUNK_SC)   // 197632
#define SMEM_LG (1024 + 4 * CHUNK_LG)   // 197632 (4-stage)

__device__ __forceinline__ uint32_t smem_u32(const void* p) {
    uint32_t a;
    asm("{ .reg .u64 t; cvta.to.shared.u64 t, %1; cvt.u32.u64 %0, t; }" : "=r"(a) : "l"(p));
    return a;
}
__device__ __forceinline__ void mbar_init(uint32_t a, uint32_t cnt) {
    asm volatile("mbarrier.init.shared.b64 [%0], %1;" :: "r"(a), "r"(cnt) : "memory");
}
__device__ __forceinline__ void mbar_expect_tx(uint32_t a, uint32_t bytes) {
    asm volatile("mbarrier.arrive.expect_tx.shared.b64 _, [%0], %1;"
                 :: "r"(a), "r"(bytes) : "memory");
}
__device__ __forceinline__ void mbar_wait(uint32_t a, uint32_t parity) {
    asm volatile(
        "{\n\t.reg .pred P;\n\t"
        "W_%=:\n\t"
        "mbarrier.try_wait.parity.acquire.cta.shared::cta.b64 P, [%0], %1, 0x989680;\n\t"
        "@P bra.uni D_%=;\n\t"
        "bra.uni W_%=;\n\t"
        "D_%=:\n\t}"
        :: "r"(a), "r"(parity) : "memory");
}
__device__ __forceinline__ void bulk_g2s(uint32_t dst, const void* src, uint32_t bytes, uint32_t mbar) {
    asm volatile(
        "cp.async.bulk.shared::cluster.global.mbarrier::complete_tx::bytes [%0], [%1], %2, [%3];"
        :: "r"(dst), "l"(src), "r"(bytes), "r"(mbar) : "memory");
}
__device__ __forceinline__ void ldsm_x4(uint32_t* r, uint32_t a) {
    asm volatile("ldmatrix.sync.aligned.m8n8.x4.shared.b16 {%0,%1,%2,%3}, [%4];"
                 : "=r"(r[0]), "=r"(r[1]), "=r"(r[2]), "=r"(r[3]) : "r"(a));
}
__device__ __forceinline__ void mma16816(float* d, const uint32_t* a, const uint32_t* b) {
    asm volatile(
        "mma.sync.aligned.m16n8k16.row.col.f32.bf16.bf16.f32 "
        "{%0,%1,%2,%3}, {%4,%5,%6,%7}, {%8,%9}, {%0,%1,%2,%3};"
        : "+f"(d[0]), "+f"(d[1]), "+f"(d[2]), "+f"(d[3])
        : "r"(a[0]), "r"(a[1]), "r"(a[2]), "r"(a[3]), "r"(b[0]), "r"(b[1]));
}
__device__ __forceinline__ void mma16816_f16(float* d, const uint32_t* a, const uint32_t* b) {
    asm volatile(
        "mma.sync.aligned.m16n8k16.row.col.f32.f16.f16.f32 "
        "{%0,%1,%2,%3}, {%4,%5,%6,%7}, {%8,%9}, {%0,%1,%2,%3};"
        : "+f"(d[0]), "+f"(d[1]), "+f"(d[2]), "+f"(d[3])
        : "r"(a[0]), "r"(a[1]), "r"(a[2]), "r"(a[3]), "r"(b[0]), "r"(b[1]));
}
__device__ __forceinline__ void split2u(float a, float b, uint32_t& h, uint32_t& l) {
    __nv_bfloat162 hh, ll;
    hh.x = __float2bfloat16(a); hh.y = __float2bfloat16(b);
    ll.x = __float2bfloat16(a - __bfloat162float(hh.x));
    ll.y = __float2bfloat16(b - __bfloat162float(hh.y));
    h = *(uint32_t*)&hh; l = *(uint32_t*)&ll;
}
__device__ __forceinline__ uint32_t pack_h2(float a, float b) {
    __half2 p = __floats2half2_rn(a, b);
    return *(uint32_t*)&p;
}

// ===========================================================================
// prep_q: gathered W rows -> swizzled bf16 hi/lo q tiles
// ===========================================================================
__global__ __launch_bounds__(256) void prep_q_kernel(
    const int* __restrict__ cand, const float* __restrict__ w,
    int Lmax, int qtotal)
{
    int i = blockIdx.x * 256 + threadIdx.x;
    if (i >= qtotal) return;
    const int quad = i & 63;
    const int crow = (i >> 6) & 2047;
    const int b    = i >> 17;
    const int k = quad * 4, chunk = k >> 6, col = k & 63;
    int c = crow < CC ? crow : CC - 1;
    int lbl = cand[b * CC + c];
    lbl = lbl < 0 ? 0 : (lbl > Lmax ? Lmax : lbl);
    float4 v = *(const float4*)(w + (size_t)lbl * CH + k);
    uint32_t h0, l0, h1, l1;
    split2u(v.x, v.y, h0, l0);
    split2u(v.z, v.w, h1, l1);
    const size_t tb = (size_t)((b * 8 + (crow >> 8)) * 4 + chunk) * TILE256B;
    const uint32_t off = SW128((crow & 255) * 128 + col * 2);
    *(uint2*)((char*)g_qt_hi + tb + off) = make_uint2(h0, h1);
    *(uint2*)((char*)g_qt_lo + tb + off) = make_uint2(l0, l1);
}

// ===========================================================================
// prep_x: ONE x read feeds both xs (k-major bf16 hi/lo) and xt (fp16 transposed)
// grid = B*16*2, block = (b, s-chunk of 64, h-half of 128). Staged in smem.
// ===========================================================================
__global__ __launch_bounds__(256) void prep_x_kernel(const float* __restrict__ x)
{
    __shared__ float t[64][129];
    const int bid = blockIdx.x;
    const int chs = bid & 15;          // s block of 64
    const int hb  = (bid >> 4) & 1;    // h half of 128
    const int b   = bid >> 5;
    const int s0 = chs * 64;
    const int h0 = hb * 128;
    const int tid = threadIdx.x;

    // stage 64 s-rows x 128 h floats
    #pragma unroll
    for (int j = 0; j < 8; j++) {
        const int q = j * 256 + tid;
        const int s = q >> 5;
        const int c4 = q & 31;
        float4 v = *(const float4*)(x + ((size_t)(b * 1024 + s0 + s)) * CH + h0 + c4 * 4);
        t[s][c4 * 4 + 0] = v.x; t[s][c4 * 4 + 1] = v.y;
        t[s][c4 * 4 + 2] = v.z; t[s][c4 * 4 + 3] = v.w;
    }
    __syncthreads();

    // --- xt: transposed fp16 tile [128h x 64s] ---
    {
        const int h = tid >> 1;
        const int half = tid & 1;
        const size_t tb = (size_t)((b * 2 + hb) * 16 + chs) * TILE128B;
        #pragma unroll
        for (int g = 0; g < 8; g++) {
            const int scol = half * 32 + g * 4;
            uint32_t p01 = pack_h2(t[scol + 0][h], t[scol + 1][h]);
            uint32_t p23 = pack_h2(t[scol + 2][h], t[scol + 3][h]);
            const uint32_t off = SW128(h * 128 + scol * 2);
            *(uint2*)((char*)g_xt_f16 + tb + off) = make_uint2(p01, p23);
        }
    }

    // --- xs: k-major bf16 hi/lo, 2 chunks (h0/64, h0/64+1), 64 rows each ---
    {
        const int sblk = chs >> 1;
        const int rowbase = (chs & 1) * 64;
        #pragma unroll
        for (int j = 0; j < 8; j++) {
            const int q = j * 256 + tid;      // 0..2047 uint2 slots
            const int cc = q >> 10;           // which chunk half
            const int r  = (q >> 4) & 63;     // local s row
            const int u  = q & 15;            // uint2 col (4 bf16 each)
            const int hcol = cc * 64 + u * 4;
            float f0 = t[r][hcol + 0], f1 = t[r][hcol + 1];
            float f2 = t[r][hcol + 2], f3 = t[r][hcol + 3];
            uint32_t h01, l01, h23, l23;
            split2u(f0, f1, h01, l01);
            split2u(f2, f3, h23, l23);
            const size_t tb = (size_t)((b * 8 + sblk) * 4 + (hb * 2 + cc)) * TILE128B;
            const uint32_t off = SW128((rowbase + r) * 128 + u * 8);
            *(uint2*)((char*)g_xs_hi + tb + off) = make_uint2(h01, h23);
            *(uint2*)((char*)g_xs_lo + tb + off) = make_uint2(l01, l23);
        }
    }
}

// ===========================================================================
// Kernel 1: scores = q . x^T (masked -> -inf), bf16 3-pass, 2-stage bulk
// ===========================================================================
__global__ __launch_bounds__(512, 1) void scores_mma_kernel(
    const int* __restrict__ masks, float* __restrict__ attn, int S, int C)
{
    extern __shared__ char dsm[];
    const uint32_t sb = smem_u32(dsm);
    const uint32_t mbar0 = sb;
    int* smask = (int*)(dsm + 16);

    const int tid = threadIdx.x;
    const int lane = tid & 31;
    const int wid = tid >> 5;
    const int wm = wid & 7;
    const int wn = wid >> 3;
    const int b  = blockIdx.z;
    const int cblk = blockIdx.y;
    const int sblk = blockIdx.x;
    const int c0 = cblk * 256;
    const int s0 = sblk * 128;

    if (tid == 0) { mbar_init(mbar0, 1); mbar_init(mbar0 + 8, 1); }
    if (tid < 128) smask[tid] = masks[(size_t)b * S + s0 + tid];
    __syncthreads();

    auto issue = [&](int ch, int stg) {
        const uint32_t base = sb + 1024 + stg * CHUNK_SC;
        const uint32_t mb = mbar0 + stg * 8;
        const size_t at = (size_t)((b * 8 + cblk) * 4 + ch) * TILE256B;
        const size_t bt = (size_t)((b * 8 + sblk) * 4 + ch) * TILE128B;
        mbar_expect_tx(mb, CHUNK_SC);
        bulk_g2s(base,                        (char*)g_qt_hi + at, TILE256B, mb);
        bulk_g2s(base + TILE256B,             (char*)g_qt_lo + at, TILE256B, mb);
        bulk_g2s(base + 2 * TILE256B,             (char*)g_xs_hi + bt, TILE128B, mb);
        bulk_g2s(base + 2 * TILE256B + TILE128B,  (char*)g_xs_lo + bt, TILE128B, mb);
    };
    if (tid == 0) { issue(0, 0); issue(1, 1); }

    const int a_r = lane & 15;
    const int a_k = (lane >> 4) * 8;
    const int b_n = (lane & 7) | (((lane >> 4) & 1) << 3);
    const int b_k = ((lane >> 3) & 1) * 8;

    float acc[2][8][4];
    #pragma unroll
    for (int i = 0; i < 2; i++)
        #pragma unroll
        for (int j = 0; j < 8; j++)
            #pragma unroll
            for (int q = 0; q < 4; q++) acc[i][j][q] = 0.f;

    int ph[2] = {0, 0};
    const int nch = 4;
    for (int ch = 0; ch < nch; ch++) {
        const int stg = ch & 1;
        mbar_wait(mbar0 + stg * 8, ph[stg]);
        ph[stg] ^= 1;

        const uint32_t uA0 = sb + 1024 + stg * CHUNK_SC;
        const uint32_t uA1 = uA0 + TILE256B;
        const uint32_t uB0 = uA1 + TILE256B;
        const uint32_t uB1 = uB0 + TILE128B;

        #pragma unroll
        for (int kk = 0; kk < 64; kk += 16) {
            uint32_t aH[2][4], aL[2][4];
            #pragma unroll
            for (int mt = 0; mt < 2; mt++) {
                uint32_t off = SW128((uint32_t)(wm * 32 + mt * 16 + a_r) * 128 + (kk + a_k) * 2);
                ldsm_x4(aH[mt], uA0 + off);
                ldsm_x4(aL[mt], uA1 + off);
            }
            uint32_t bH[4][4], bL[4][4];
            #pragma unroll
            for (int t = 0; t < 4; t++) {
                uint32_t off = SW128((uint32_t)(wn * 64 + t * 16 + b_n) * 128 + (kk + b_k) * 2);
                ldsm_x4(bH[t], uB0 + off);
                ldsm_x4(bL[t], uB1 + off);
            }
            #pragma unroll
            for (int mt = 0; mt < 2; mt++)
                #pragma unroll
                for (int t = 0; t < 4; t++)
                    #pragma unroll
                    for (int hf = 0; hf < 2; hf++)
                        mma16816(acc[mt][2 * t + hf], aH[mt], &bH[t][hf * 2]);
            #pragma unroll
            for (int mt = 0; mt < 2; mt++)
                #pragma unroll
                for (int t = 0; t < 4; t++)
                    #pragma unroll
                    for (int hf = 0; hf < 2; hf++)
                        mma16816(acc[mt][2 * t + hf], aH[mt], &bL[t][hf * 2]);
            #pragma unroll
            for (int mt = 0; mt < 2; mt++)
                #pragma unroll
                for (int t = 0; t < 4; t++)
                    #pragma unroll
                    for (int hf = 0; hf < 2; hf++)
                        mma16816(acc[mt][2 * t + hf], aL[mt], &bH[t][hf * 2]);
        }
        __syncthreads();
        if (tid == 0 && ch + 2 < nch) issue(ch + 2, stg);
    }

    #pragma unroll
    for (int mt = 0; mt < 2; mt++) {
        const int r0 = wm * 32 + mt * 16 + (lane >> 2);
        #pragma unroll
        for (int nt = 0; nt < 8; nt++) {
            const int sl = wn * 64 + nt * 8 + (lane & 3) * 2;
            const float ninf = -INFINITY;
            float2 o0, o1;
            o0.x = smask[sl]     ? acc[mt][nt][0] : ninf;
            o0.y = smask[sl + 1] ? acc[mt][nt][1] : ninf;
            o1.x = smask[sl]     ? acc[mt][nt][2] : ninf;
            o1.y = smask[sl + 1] ? acc[mt][nt][3] : ninf;
            int c = c0 + r0;
            if (c < C)
                *(float2*)(attn + ((size_t)b * C + c) * S + s0 + sl) = o0;
            if (c + 8 < C)
                *(float2*)(attn + ((size_t)b * C + c + 8) * S + s0 + sl) = o1;
        }
    }
}

// ===========================================================================
// Kernel 2: fused softmax — warp/row; writes fp32 attn + swizzled fp16 tiles
// ===========================================================================
__global__ __launch_bounds__(256) void softmax_fused_kernel(
    float* __restrict__ attn, int S, int C)
{
    const int lane = threadIdx.x & 31;
    const int wrp  = threadIdx.x >> 5;
    const int row = blockIdx.x * 8 + wrp;
    const int b = row / C;
    const int c = row - b * C;
    float* p = attn + (size_t)row * S;

    float4 v[8];
    float m = -INFINITY;
    #pragma unroll
    for (int f = 0; f < 8; f++) {
        v[f] = ((const float4*)p)[lane + (f << 5)];
        m = fmaxf(m, fmaxf(fmaxf(v[f].x, v[f].y), fmaxf(v[f].z, v[f].w)));
    }
    #pragma unroll
    for (int o = 16; o > 0; o >>= 1) m = fmaxf(m, __shfl_xor_sync(0xffffffffu, m, o));

    float s = 0.f;
    #pragma unroll
    for (int f = 0; f < 8; f++) {
        v[f].x = __expf(v[f].x - m); v[f].y = __expf(v[f].y - m);
        v[f].z = __expf(v[f].z - m); v[f].w = __expf(v[f].w - m);
        s += (v[f].x + v[f].y) + (v[f].z + v[f].w);
    }
    #pragma unroll
    for (int o = 16; o > 0; o >>= 1) s += __shfl_xor_sync(0xffffffffu, s, o);
    const float inv = 1.0f / s;

    const size_t tile0 = (size_t)((b * 8 + (c >> 8)) * 16) * TILE256B;
    const uint32_t rowoff = (uint32_t)(c & 255) * 128;
    #pragma unroll
    for (int f = 0; f < 8; f++) {
        float4 o;
        o.x = v[f].x * inv; o.y = v[f].y * inv;
        o.z = v[f].z * inv; o.w = v[f].w * inv;
        const int idx = lane + (f << 5);
        ((float4*)p)[idx] = o;
        const int chunk = idx >> 4;
        const uint32_t off = SW128(rowoff + (idx & 15) * 8);
        const size_t byteoff = tile0 + (size_t)chunk * TILE256B + off;
        *(uint2*)((char*)g_at_f16 + byteoff) =
            make_uint2(pack_h2(o.x, o.y), pack_h2(o.z, o.w));
    }
}

// ===========================================================================
// Kernel 3: logits = attn . x — single-pass fp16 HMMA, 4-stage bulk pipeline
// ===========================================================================
__global__ __launch_bounds__(512, 1) void logits_mma_kernel(
    float* __restrict__ out, int H, int C)
{
    extern __shared__ char dsm[];
    const uint32_t sb = smem_u32(dsm);
    const uint32_t mbar0 = sb;

    const int tid = threadIdx.x;
    const int lane = tid & 31;
    const int wid = tid >> 5;
    const int wm = wid & 7;
    const int wn = wid >> 3;
    const int b  = blockIdx.z;
    const int cblk = blockIdx.y;
    const int hb = blockIdx.x;
    const int c0 = cblk * 256;
    const int h0 = hb * 128;

    if (tid == 0) {
        #pragma unroll
        for (int s = 0; s < 4; s++) mbar_init(mbar0 + s * 8, 1);
    }
    __syncthreads();

    auto issue = [&](int ch, int stg) {
        const uint32_t base = sb + 1024 + stg * CHUNK_LG;
        const uint32_t mb = mbar0 + stg * 8;
        const size_t at = (size_t)((b * 8 + cblk) * 16 + ch) * TILE256B;
        const size_t bt = (size_t)((b * 2 + hb) * 16 + ch) * TILE128B;
        mbar_expect_tx(mb, CHUNK_LG);
        bulk_g2s(base,            (char*)g_at_f16 + at, TILE256B, mb);
        bulk_g2s(base + TILE256B, (char*)g_xt_f16 + bt, TILE128B, mb);
    };
    if (tid == 0) { issue(0, 0); issue(1, 1); issue(2, 2); issue(3, 3); }

    const int a_r = lane & 15;
    const int a_k = (lane >> 4) * 8;
    const int b_n = (lane & 7) | (((lane >> 4) & 1) << 3);
    const int b_k = ((lane >> 3) & 1) * 8;

    float acc[2][8][4];
    #pragma unroll
    for (int i = 0; i < 2; i++)
        #pragma unroll
        for (int j = 0; j < 8; j++)
            #pragma unroll
            for (int q = 0; q < 4; q++) acc[i][j][q] = 0.f;

    int ph[4] = {0, 0, 0, 0};
    const int nch = 16;
    for (int ch = 0; ch < nch; ch++) {
        const int stg = ch & 3;
        mbar_wait(mbar0 + stg * 8, ph[stg]);
        ph[stg] ^= 1;

        const uint32_t uA = sb + 1024 + stg * CHUNK_LG;
        const uint32_t uB = uA + TILE256B;

        #pragma unroll
        for (int kk = 0; kk < 64; kk += 16) {
            uint32_t aF[2][4];
            #pragma unroll
            for (int mt = 0; mt < 2; mt++) {
                uint32_t off = SW128((uint32_t)(wm * 32 + mt * 16 + a_r) * 128 + (kk + a_k) * 2);
                ldsm_x4(aF[mt], uA + off);
            }
            uint32_t bF[4][4];
            #pragma unroll
            for (int t = 0; t < 4; t++) {
                uint32_t off = SW128((uint32_t)(wn * 64 + t * 16 + b_n) * 128 + (kk + b_k) * 2);
                ldsm_x4(bF[t], uB + off);
            }
            #pragma unroll
            for (int mt = 0; mt < 2; mt++)
                #pragma unroll
                for (int t = 0; t < 4; t++)
                    #pragma unroll
                    for (int hf = 0; hf < 2; hf++)
                        mma16816_f16(acc[mt][2 * t + hf], aF[mt], &bF[t][hf * 2]);
        }
        __syncthreads();
        if (tid == 0 && ch + 4 < nch) issue(ch + 4, stg);
    }

    #pragma unroll
    for (int mt = 0; mt < 2; mt++) {
        const int r0 = wm * 32 + mt * 16 + (lane >> 2);
        #pragma unroll
        for (int nt = 0; nt < 8; nt++) {
            const int hl = wn * 64 + nt * 8 + (lane & 3) * 2;
            int c = c0 + r0;
            if (c < C)
                *(float2*)(out + ((size_t)b * C + c) * H + h0 + hl) =
                    make_float2(acc[mt][nt][0], acc[mt][nt][1]);
            if (c + 8 < C)
                *(float2*)(out + ((size_t)b * C + c + 8) * H + h0 + hl) =
                    make_float2(acc[mt][nt][2], acc[mt][nt][3]);
        }
    }
}

// ===========================================================================
// Launch
// ===========================================================================
extern "C" void kernel_launch(void* const* d_in, const int* in_sizes, int n_in,
                              void* d_out, int out_size)
{
    const float* x     = (const float*)d_in[0];
    const int*   masks = (const int*)d_in[1];
    const int*   cand  = (const int*)d_in[2];
    const float* w     = (const float*)d_in[3];

    const long long n0 = in_sizes[0];
    const long long n1 = in_sizes[1];
    const long long n2 = in_sizes[2];
    const long long n3 = in_sizes[3];

    const int H  = (int)(n0 / n1);
    const int HS = (int)((long long)out_size / n2);
    const int S  = HS - H;
    const int B  = (int)(n1 / S);
    const int C  = (int)(n2 / B);
    const int Lmax = (int)(n3 / H) - 1;

    float* logits = (float*)d_out;
    float* attn   = logits + (size_t)B * C * H;

    static bool attr_set = false;
    if (!attr_set) {
        cudaFuncSetAttribute(scores_mma_kernel, cudaFuncAttributeMaxDynamicSharedMemorySize, SMEM_SC);
        cudaFuncSetAttribute(logits_mma_kernel, cudaFuncAttributeMaxDynamicSharedMemorySize, SMEM_LG);
        attr_set = true;
    }

    const int qtotal = B * 2048 * 64;
    prep_q_kernel<<<(qtotal + 255) / 256, 256>>>(cand, w, Lmax, qtotal);

    prep_x_kernel<<<B * 16 * 2, 256>>>(x);

    dim3 g1(S / 128, 8, B);
    scores_mma_kernel<<<g1, 512, SMEM_SC>>>(masks, attn, S, C);

    dim3 g2((unsigned)((size_t)B * C / 8));
    softmax_fused_kernel<<<g2, 256>>>(attn, S, C);

    dim3 g3(H / 128, 8, B);
    logits_mma_kernel<<<g3, 512, SMEM_LG>>>(logits, H, C);
}

// round 16
// speedup vs baseline: 1.8240x; 1.0242x over previous
#include <cuda_runtime.h>
#include <cuda_bf16.h>
#include <cuda_fp16.h>
#include <math.h>
#include <stdint.h>

// Problem shape (validated across passing rounds)
#define CB 16
#define CS 1024
#define CH 256
#define CC 2000

#define SW128(o) ((o) ^ (((o) >> 3) & 0x70))
#define TILE256B 32768              // 256 rows x 128B
#define TILE128B 16384              // 128 rows x 128B
#define CHUNK_SC (2 * TILE256B + 2 * TILE128B)   // 98304 (scores: bf16 hi/lo)
#define CHUNK_LGP (2 * (TILE256B + TILE128B))    // 98304 (logits: fp16, chunk PAIR)

// scores A: q tiles  [b][cblk 8][chunk 4][256x64] bf16 hi/lo
__device__ __nv_bfloat16 g_qt_hi[512 * 16384];
__device__ __nv_bfloat16 g_qt_lo[512 * 16384];
// scores B: x tiles  [b][sblk 8][chunk 4][128x64] bf16 hi/lo
__device__ __nv_bfloat16 g_xs_hi[512 * 8192];
__device__ __nv_bfloat16 g_xs_lo[512 * 8192];
// logits B: x^T tiles [b][hblk 2][chunk 16][128x64] fp16
__device__ __half g_xt_f16[512 * 8192];
// logits A: attention tiles [b][cblk 8][chunk 16][256x64] fp16 (from softmax)
__device__ __half g_at_f16[2048 * 16384];

#define SMEM_SC (1024 + 2 * CHUNK_SC)    // 197632
#define SMEM_LG (1024 + 2 * CHUNK_LGP)   // 197632

__device__ __forceinline__ uint32_t smem_u32(const void* p) {
    uint32_t a;
    asm("{ .reg .u64 t; cvta.to.shared.u64 t, %1; cvt.u32.u64 %0, t; }" : "=r"(a) : "l"(p));
    return a;
}
__device__ __forceinline__ void mbar_init(uint32_t a, uint32_t cnt) {
    asm volatile("mbarrier.init.shared.b64 [%0], %1;" :: "r"(a), "r"(cnt) : "memory");
}
__device__ __forceinline__ void mbar_expect_tx(uint32_t a, uint32_t bytes) {
    asm volatile("mbarrier.arrive.expect_tx.shared.b64 _, [%0], %1;"
                 :: "r"(a), "r"(bytes) : "memory");
}
__device__ __forceinline__ void mbar_wait(uint32_t a, uint32_t parity) {
    asm volatile(
        "{\n\t.reg .pred P;\n\t"
        "W_%=:\n\t"
        "mbarrier.try_wait.parity.acquire.cta.shared::cta.b64 P, [%0], %1, 0x989680;\n\t"
        "@P bra.uni D_%=;\n\t"
        "bra.uni W_%=;\n\t"
        "D_%=:\n\t}"
        :: "r"(a), "r"(parity) : "memory");
}
__device__ __forceinline__ void bulk_g2s(uint32_t dst, const void* src, uint32_t bytes, uint32_t mbar) {
    asm volatile(
        "cp.async.bulk.shared::cluster.global.mbarrier::complete_tx::bytes [%0], [%1], %2, [%3];"
        :: "r"(dst), "l"(src), "r"(bytes), "r"(mbar) : "memory");
}
__device__ __forceinline__ void ldsm_x4(uint32_t* r, uint32_t a) {
    asm volatile("ldmatrix.sync.aligned.m8n8.x4.shared.b16 {%0,%1,%2,%3}, [%4];"
                 : "=r"(r[0]), "=r"(r[1]), "=r"(r[2]), "=r"(r[3]) : "r"(a));
}
__device__ __forceinline__ void mma16816(float* d, const uint32_t* a, const uint32_t* b) {
    asm volatile(
        "mma.sync.aligned.m16n8k16.row.col.f32.bf16.bf16.f32 "
        "{%0,%1,%2,%3}, {%4,%5,%6,%7}, {%8,%9}, {%0,%1,%2,%3};"
        : "+f"(d[0]), "+f"(d[1]), "+f"(d[2]), "+f"(d[3])
        : "r"(a[0]), "r"(a[1]), "r"(a[2]), "r"(a[3]), "r"(b[0]), "r"(b[1]));
}
__device__ __forceinline__ void mma16816_f16(float* d, const uint32_t* a, const uint32_t* b) {
    asm volatile(
        "mma.sync.aligned.m16n8k16.row.col.f32.f16.f16.f32 "
        "{%0,%1,%2,%3}, {%4,%5,%6,%7}, {%8,%9}, {%0,%1,%2,%3};"
        : "+f"(d[0]), "+f"(d[1]), "+f"(d[2]), "+f"(d[3])
        : "r"(a[0]), "r"(a[1]), "r"(a[2]), "r"(a[3]), "r"(b[0]), "r"(b[1]));
}
__device__ __forceinline__ void split2u(float a, float b, uint32_t& h, uint32_t& l) {
    __nv_bfloat162 hh, ll;
    hh.x = __float2bfloat16(a); hh.y = __float2bfloat16(b);
    ll.x = __float2bfloat16(a - __bfloat162float(hh.x));
    ll.y = __float2bfloat16(b - __bfloat162float(hh.y));
    h = *(uint32_t*)&hh; l = *(uint32_t*)&ll;
}
__device__ __forceinline__ uint32_t pack_h2(float a, float b) {
    __half2 p = __floats2half2_rn(a, b);
    return *(uint32_t*)&p;
}

// ===========================================================================
// merged prep: blocks [0, 512) = x path (staged transpose + xs tiles),
//              blocks [512, ...) = q gather path.
// ===========================================================================
__global__ __launch_bounds__(256) void prep_kernel(
    const int* __restrict__ cand, const float* __restrict__ w,
    const float* __restrict__ x, int Lmax, int qtotal)
{
    __shared__ float t[64][129];
    const int tid = threadIdx.x;

    if (blockIdx.x < 512) {
        // ---------------- x path ----------------
        const int bid = blockIdx.x;
        const int chs = bid & 15;          // s block of 64
        const int hb  = (bid >> 4) & 1;    // h half of 128
        const int b   = bid >> 5;
        const int s0 = chs * 64;
        const int h0 = hb * 128;

        #pragma unroll
        for (int j = 0; j < 8; j++) {
            const int q = j * 256 + tid;
            const int s = q >> 5;
            const int c4 = q & 31;
            float4 v = *(const float4*)(x + ((size_t)(b * 1024 + s0 + s)) * CH + h0 + c4 * 4);
            t[s][c4 * 4 + 0] = v.x; t[s][c4 * 4 + 1] = v.y;
            t[s][c4 * 4 + 2] = v.z; t[s][c4 * 4 + 3] = v.w;
        }
        __syncthreads();

        // xt: transposed fp16 tile [128h x 64s]
        {
            const int h = tid >> 1;
            const int half = tid & 1;
            const size_t tb = (size_t)((b * 2 + hb) * 16 + chs) * TILE128B;
            #pragma unroll
            for (int g = 0; g < 8; g++) {
                const int scol = half * 32 + g * 4;
                uint32_t p01 = pack_h2(t[scol + 0][h], t[scol + 1][h]);
                uint32_t p23 = pack_h2(t[scol + 2][h], t[scol + 3][h]);
                const uint32_t off = SW128(h * 128 + scol * 2);
                *(uint2*)((char*)g_xt_f16 + tb + off) = make_uint2(p01, p23);
            }
        }

        // xs: k-major bf16 hi/lo, 2 chunks, 64 rows each
        {
            const int sblk = chs >> 1;
            const int rowbase = (chs & 1) * 64;
            #pragma unroll
            for (int j = 0; j < 8; j++) {
                const int q = j * 256 + tid;
                const int cc = q >> 10;
                const int r  = (q >> 4) & 63;
                const int u  = q & 15;
                const int hcol = cc * 64 + u * 4;
                float f0 = t[r][hcol + 0], f1 = t[r][hcol + 1];
                float f2 = t[r][hcol + 2], f3 = t[r][hcol + 3];
                uint32_t h01, l01, h23, l23;
                split2u(f0, f1, h01, l01);
                split2u(f2, f3, h23, l23);
                const size_t tb = (size_t)((b * 8 + sblk) * 4 + (hb * 2 + cc)) * TILE128B;
                const uint32_t off = SW128((rowbase + r) * 128 + u * 8);
                *(uint2*)((char*)g_xs_hi + tb + off) = make_uint2(h01, h23);
                *(uint2*)((char*)g_xs_lo + tb + off) = make_uint2(l01, l23);
            }
        }
    } else {
        // ---------------- q path ----------------
        int i = (blockIdx.x - 512) * 256 + tid;
        if (i >= qtotal) return;
        const int quad = i & 63;
        const int crow = (i >> 6) & 2047;
        const int b    = i >> 17;
        const int k = quad * 4, chunk = k >> 6, col = k & 63;
        int c = crow < CC ? crow : CC - 1;
        int lbl = cand[b * CC + c];
        lbl = lbl < 0 ? 0 : (lbl > Lmax ? Lmax : lbl);
        float4 v = *(const float4*)(w + (size_t)lbl * CH + k);
        uint32_t h0, l0, h1, l1;
        split2u(v.x, v.y, h0, l0);
        split2u(v.z, v.w, h1, l1);
        const size_t tb = (size_t)((b * 8 + (crow >> 8)) * 4 + chunk) * TILE256B;
        const uint32_t off = SW128((crow & 255) * 128 + col * 2);
        *(uint2*)((char*)g_qt_hi + tb + off) = make_uint2(h0, h1);
        *(uint2*)((char*)g_qt_lo + tb + off) = make_uint2(l0, l1);
    }
}

// ===========================================================================
// Kernel 1: scores = q . x^T (masked -> -inf), bf16 3-pass, 2-stage bulk
// ===========================================================================
__global__ __launch_bounds__(512, 1) void scores_mma_kernel(
    const int* __restrict__ masks, float* __restrict__ attn, int S, int C)
{
    extern __shared__ char dsm[];
    const uint32_t sb = smem_u32(dsm);
    const uint32_t mbar0 = sb;
    int* smask = (int*)(dsm + 16);

    const int tid = threadIdx.x;
    const int lane = tid & 31;
    const int wid = tid >> 5;
    const int wm = wid & 7;
    const int wn = wid >> 3;
    const int b  = blockIdx.z;
    const int cblk = blockIdx.y;
    const int sblk = blockIdx.x;
    const int c0 = cblk * 256;
    const int s0 = sblk * 128;

    if (tid == 0) { mbar_init(mbar0, 1); mbar_init(mbar0 + 8, 1); }
    if (tid < 128) smask[tid] = masks[(size_t)b * S + s0 + tid];
    __syncthreads();

    auto issue = [&](int ch, int stg) {
        const uint32_t base = sb + 1024 + stg * CHUNK_SC;
        const uint32_t mb = mbar0 + stg * 8;
        const size_t at = (size_t)((b * 8 + cblk) * 4 + ch) * TILE256B;
        const size_t bt = (size_t)((b * 8 + sblk) * 4 + ch) * TILE128B;
        mbar_expect_tx(mb, CHUNK_SC);
        bulk_g2s(base,                        (char*)g_qt_hi + at, TILE256B, mb);
        bulk_g2s(base + TILE256B,             (char*)g_qt_lo + at, TILE256B, mb);
        bulk_g2s(base + 2 * TILE256B,             (char*)g_xs_hi + bt, TILE128B, mb);
        bulk_g2s(base + 2 * TILE256B + TILE128B,  (char*)g_xs_lo + bt, TILE128B, mb);
    };
    if (tid == 0) { issue(0, 0); issue(1, 1); }

    const int a_r = lane & 15;
    const int a_k = (lane >> 4) * 8;
    const int b_n = (lane & 7) | (((lane >> 4) & 1) << 3);
    const int b_k = ((lane >> 3) & 1) * 8;

    float acc[2][8][4];
    #pragma unroll
    for (int i = 0; i < 2; i++)
        #pragma unroll
        for (int j = 0; j < 8; j++)
            #pragma unroll
            for (int q = 0; q < 4; q++) acc[i][j][q] = 0.f;

    int ph[2] = {0, 0};
    const int nch = 4;
    for (int ch = 0; ch < nch; ch++) {
        const int stg = ch & 1;
        mbar_wait(mbar0 + stg * 8, ph[stg]);
        ph[stg] ^= 1;

        const uint32_t uA0 = sb + 1024 + stg * CHUNK_SC;
        const uint32_t uA1 = uA0 + TILE256B;
        const uint32_t uB0 = uA1 + TILE256B;
        const uint32_t uB1 = uB0 + TILE128B;

        #pragma unroll
        for (int kk = 0; kk < 64; kk += 16) {
            uint32_t aH[2][4], aL[2][4];
            #pragma unroll
            for (int mt = 0; mt < 2; mt++) {
                uint32_t off = SW128((uint32_t)(wm * 32 + mt * 16 + a_r) * 128 + (kk + a_k) * 2);
                ldsm_x4(aH[mt], uA0 + off);
                ldsm_x4(aL[mt], uA1 + off);
            }
            uint32_t bH[4][4], bL[4][4];
            #pragma unroll
            for (int t = 0; t < 4; t++) {
                uint32_t off = SW128((uint32_t)(wn * 64 + t * 16 + b_n) * 128 + (kk + b_k) * 2);
                ldsm_x4(bH[t], uB0 + off);
                ldsm_x4(bL[t], uB1 + off);
            }
            #pragma unroll
            for (int mt = 0; mt < 2; mt++)
                #pragma unroll
                for (int t = 0; t < 4; t++)
                    #pragma unroll
                    for (int hf = 0; hf < 2; hf++)
                        mma16816(acc[mt][2 * t + hf], aH[mt], &bH[t][hf * 2]);
            #pragma unroll
            for (int mt = 0; mt < 2; mt++)
                #pragma unroll
                for (int t = 0; t < 4; t++)
                    #pragma unroll
                    for (int hf = 0; hf < 2; hf++)
                        mma16816(acc[mt][2 * t + hf], aH[mt], &bL[t][hf * 2]);
            #pragma unroll
            for (int mt = 0; mt < 2; mt++)
                #pragma unroll
                for (int t = 0; t < 4; t++)
                    #pragma unroll
                    for (int hf = 0; hf < 2; hf++)
                        mma16816(acc[mt][2 * t + hf], aL[mt], &bH[t][hf * 2]);
        }
        __syncthreads();
        if (tid == 0 && ch + 2 < nch) issue(ch + 2, stg);
    }

    #pragma unroll
    for (int mt = 0; mt < 2; mt++) {
        const int r0 = wm * 32 + mt * 16 + (lane >> 2);
        #pragma unroll
        for (int nt = 0; nt < 8; nt++) {
            const int sl = wn * 64 + nt * 8 + (lane & 3) * 2;
            const float ninf = -INFINITY;
            float2 o0, o1;
            o0.x = smask[sl]     ? acc[mt][nt][0] : ninf;
            o0.y = smask[sl + 1] ? acc[mt][nt][1] : ninf;
            o1.x = smask[sl]     ? acc[mt][nt][2] : ninf;
            o1.y = smask[sl + 1] ? acc[mt][nt][3] : ninf;
            int c = c0 + r0;
            if (c < C)
                *(float2*)(attn + ((size_t)b * C + c) * S + s0 + sl) = o0;
            if (c + 8 < C)
                *(float2*)(attn + ((size_t)b * C + c + 8) * S + s0 + sl) = o1;
        }
    }
}

// ===========================================================================
// Kernel 2: fused softmax — warp/row; writes fp32 attn + swizzled fp16 tiles
// ===========================================================================
__global__ __launch_bounds__(256) void softmax_fused_kernel(
    float* __restrict__ attn, int S, int C)
{
    const int lane = threadIdx.x & 31;
    const int wrp  = threadIdx.x >> 5;
    const int row = blockIdx.x * 8 + wrp;
    const int b = row / C;
    const int c = row - b * C;
    float* p = attn + (size_t)row * S;

    float4 v[8];
    float m = -INFINITY;
    #pragma unroll
    for (int f = 0; f < 8; f++) {
        v[f] = ((const float4*)p)[lane + (f << 5)];
        m = fmaxf(m, fmaxf(fmaxf(v[f].x, v[f].y), fmaxf(v[f].z, v[f].w)));
    }
    #pragma unroll
    for (int o = 16; o > 0; o >>= 1) m = fmaxf(m, __shfl_xor_sync(0xffffffffu, m, o));

    float s = 0.f;
    #pragma unroll
    for (int f = 0; f < 8; f++) {
        v[f].x = __expf(v[f].x - m); v[f].y = __expf(v[f].y - m);
        v[f].z = __expf(v[f].z - m); v[f].w = __expf(v[f].w - m);
        s += (v[f].x + v[f].y) + (v[f].z + v[f].w);
    }
    #pragma unroll
    for (int o = 16; o > 0; o >>= 1) s += __shfl_xor_sync(0xffffffffu, s, o);
    const float inv = 1.0f / s;

    const size_t tile0 = (size_t)((b * 8 + (c >> 8)) * 16) * TILE256B;
    const uint32_t rowoff = (uint32_t)(c & 255) * 128;
    #pragma unroll
    for (int f = 0; f < 8; f++) {
        float4 o;
        o.x = v[f].x * inv; o.y = v[f].y * inv;
        o.z = v[f].z * inv; o.w = v[f].w * inv;
        const int idx = lane + (f << 5);
        ((float4*)p)[idx] = o;
        const int chunk = idx >> 4;
        const uint32_t off = SW128(rowoff + (idx & 15) * 8);
        const size_t byteoff = tile0 + (size_t)chunk * TILE256B + off;
        *(uint2*)((char*)g_at_f16 + byteoff) =
            make_uint2(pack_h2(o.x, o.y), pack_h2(o.z, o.w));
    }
}

// ===========================================================================
// Kernel 3: logits = attn . x — fp16 HMMA, PAIRED chunks (k=128/stage),
// 2 bulk copies per stage, 2-stage pipeline
// ===========================================================================
__global__ __launch_bounds__(512, 1) void logits_mma_kernel(
    float* __restrict__ out, int H, int C)
{
    extern __shared__ char dsm[];
    const uint32_t sb = smem_u32(dsm);
    const uint32_t mbar0 = sb;

    const int tid = threadIdx.x;
    const int lane = tid & 31;
    const int wid = tid >> 5;
    const int wm = wid & 7;
    const int wn = wid >> 3;
    const int b  = blockIdx.z;
    const int cblk = blockIdx.y;
    const int hb = blockIdx.x;
    const int c0 = cblk * 256;
    const int h0 = hb * 128;

    if (tid == 0) { mbar_init(mbar0, 1); mbar_init(mbar0 + 8, 1); }
    __syncthreads();

    // pr = chunk-pair index (each covers chunks 2*pr, 2*pr+1 — contiguous in tiles)
    auto issue = [&](int pr, int stg) {
        const uint32_t base = sb + 1024 + stg * CHUNK_LGP;
        const uint32_t mb = mbar0 + stg * 8;
        const size_t at = (size_t)((b * 8 + cblk) * 16 + 2 * pr) * TILE256B;
        const size_t bt = (size_t)((b * 2 + hb) * 16 + 2 * pr) * TILE128B;
        mbar_expect_tx(mb, CHUNK_LGP);
        bulk_g2s(base,                (char*)g_at_f16 + at, 2 * TILE256B, mb);
        bulk_g2s(base + 2 * TILE256B, (char*)g_xt_f16 + bt, 2 * TILE128B, mb);
    };
    if (tid == 0) { issue(0, 0); issue(1, 1); }

    const int a_r = lane & 15;
    const int a_k = (lane >> 4) * 8;
    const int b_n = (lane & 7) | (((lane >> 4) & 1) << 3);
    const int b_k = ((lane >> 3) & 1) * 8;

    float acc[2][8][4];
    #pragma unroll
    for (int i = 0; i < 2; i++)
        #pragma unroll
        for (int j = 0; j < 8; j++)
            #pragma unroll
            for (int q = 0; q < 4; q++) acc[i][j][q] = 0.f;

    int ph[2] = {0, 0};
    const int npr = 8;                     // 16 chunks / 2
    for (int pr = 0; pr < npr; pr++) {
        const int stg = pr & 1;
        mbar_wait(mbar0 + stg * 8, ph[stg]);
        ph[stg] ^= 1;

        const uint32_t baseA = sb + 1024 + stg * CHUNK_LGP;
        const uint32_t baseB = baseA + 2 * TILE256B;

        #pragma unroll
        for (int sub = 0; sub < 2; sub++) {
            const uint32_t uA = baseA + sub * TILE256B;
            const uint32_t uB = baseB + sub * TILE128B;
            #pragma unroll
            for (int kk = 0; kk < 64; kk += 16) {
                uint32_t aF[2][4];
                #pragma unroll
                for (int mt = 0; mt < 2; mt++) {
                    uint32_t off = SW128((uint32_t)(wm * 32 + mt * 16 + a_r) * 128 + (kk + a_k) * 2);
                    ldsm_x4(aF[mt], uA + off);
                }
                uint32_t bF[4][4];
                #pragma unroll
                for (int t = 0; t < 4; t++) {
                    uint32_t off = SW128((uint32_t)(wn * 64 + t * 16 + b_n) * 128 + (kk + b_k) * 2);
                    ldsm_x4(bF[t], uB + off);
                }
                #pragma unroll
                for (int mt = 0; mt < 2; mt++)
                    #pragma unroll
                    for (int t = 0; t < 4; t++)
                        #pragma unroll
                        for (int hf = 0; hf < 2; hf++)
                            mma16816_f16(acc[mt][2 * t + hf], aF[mt], &bF[t][hf * 2]);
            }
        }
        __syncthreads();
        if (tid == 0 && pr + 2 < npr) issue(pr + 2, stg);
    }

    #pragma unroll
    for (int mt = 0; mt < 2; mt++) {
        const int r0 = wm * 32 + mt * 16 + (lane >> 2);
        #pragma unroll
        for (int nt = 0; nt < 8; nt++) {
            const int hl = wn * 64 + nt * 8 + (lane & 3) * 2;
            int c = c0 + r0;
            if (c < C)
                *(float2*)(out + ((size_t)b * C + c) * H + h0 + hl) =
                    make_float2(acc[mt][nt][0], acc[mt][nt][1]);
            if (c + 8 < C)
                *(float2*)(out + ((size_t)b * C + c + 8) * H + h0 + hl) =
                    make_float2(acc[mt][nt][2], acc[mt][nt][3]);
        }
    }
}

// ===========================================================================
// Launch
// ===========================================================================
extern "C" void kernel_launch(void* const* d_in, const int* in_sizes, int n_in,
                              void* d_out, int out_size)
{
    const float* x     = (const float*)d_in[0];
    const int*   masks = (const int*)d_in[1];
    const int*   cand  = (const int*)d_in[2];
    const float* w     = (const float*)d_in[3];

    const long long n0 = in_sizes[0];
    const long long n1 = in_sizes[1];
    const long long n2 = in_sizes[2];
    const long long n3 = in_sizes[3];

    const int H  = (int)(n0 / n1);
    const int HS = (int)((long long)out_size / n2);
    const int S  = HS - H;
    const int B  = (int)(n1 / S);
    const int C  = (int)(n2 / B);
    const int Lmax = (int)(n3 / H) - 1;

    float* logits = (float*)d_out;
    float* attn   = logits + (size_t)B * C * H;

    static bool attr_set = false;
    if (!attr_set) {
        cudaFuncSetAttribute(scores_mma_kernel, cudaFuncAttributeMaxDynamicSharedMemorySize, SMEM_SC);
        cudaFuncSetAttribute(logits_mma_kernel, cudaFuncAttributeMaxDynamicSharedMemorySize, SMEM_LG);
        attr_set = true;
    }

    const int qtotal = B * 2048 * 64;
    const int qblocks = (qtotal + 255) / 256;
    prep_kernel<<<512 + qblocks, 256>>>(cand, w, x, Lmax, qtotal);

    dim3 g1(S / 128, 8, B);
    scores_mma_kernel<<<g1, 512, SMEM_SC>>>(masks, attn, S, C);

    dim3 g2((unsigned)((size_t)B * C / 8));
    softmax_fused_kernel<<<g2, 256>>>(attn, S, C);

    dim3 g3(H / 128, 8, B);
    logits_mma_kernel<<<g3, 512, SMEM_LG>>>(logits, H, C);
}